// round 1
// baseline (speedup 1.0000x reference)
#include <cuda_runtime.h>
#include <cstdint>
#include <math.h>

#define NN    50000
#define EE    800000
#define DIN   32
#define DLAT  128
#define DOUTD 10
#define GG    256
#define KHOPS 3

// Output layout: (y_pred [G,10], mu [N,128], std [N,128], y [G,10]) flattened
#define O_YPRED 0
#define O_MU    (GG*DOUTD)
#define O_STD   (O_MU + (size_t)NN*DLAT)
#define O_Y     (O_STD + (size_t)NN*DLAT)

// ---------------- scratch (__device__ globals, no allocs) ----------------
__device__ int   s_degi[NN];
__device__ float s_dinv[NN];
__device__ int   s_rowptr[NN+1];
__device__ int   s_cursor[NN];
__device__ int   s_srcs[EE];
__device__ float s_h[(size_t)NN*DLAT];
__device__ float s_p[(size_t)NN*DLAT];
__device__ float s_g[(size_t)NN*DLAT];
__device__ float s_t[(size_t)NN*DLAT];
__device__ float s_dec[(size_t)NN*256];
__device__ float s_gsum[GG*DOUTD];
__device__ int   s_gcnt[GG];

// ---------------- small kernels ----------------
__global__ void k_count(const int* __restrict__ dst, int* __restrict__ degi, int e_cnt) {
    int e = blockIdx.x*256 + threadIdx.x;
    if (e < e_cnt) atomicAdd(&degi[dst[e]], 1);
}

__global__ void k_dinv(const int* __restrict__ degi, float* __restrict__ dinv, int n) {
    int i = blockIdx.x*256 + threadIdx.x;
    if (i < n) dinv[i] = rsqrtf((float)degi[i] + 1.0f);
}

// single-block exclusive scan (N=50000 -> 49 chunk iterations)
__global__ void k_scan(const int* __restrict__ cnt, int* __restrict__ rowptr,
                       int* __restrict__ cursor, int n) {
    __shared__ int tmp[1024];
    __shared__ int carry;
    if (threadIdx.x == 0) carry = 0;
    __syncthreads();
    for (int base = 0; base < n; base += 1024) {
        int i = base + threadIdx.x;
        int v = (i < n) ? cnt[i] : 0;
        tmp[threadIdx.x] = v;
        __syncthreads();
        for (int off = 1; off < 1024; off <<= 1) {
            int addend = (threadIdx.x >= off) ? tmp[threadIdx.x - off] : 0;
            __syncthreads();
            tmp[threadIdx.x] += addend;
            __syncthreads();
        }
        int incl = tmp[threadIdx.x];
        int c = carry;
        if (i < n) { int e = c + incl - v; rowptr[i] = e; cursor[i] = e; }
        __syncthreads();
        if (threadIdx.x == 0) carry = c + tmp[1023];
        __syncthreads();
    }
    if (threadIdx.x == 0) rowptr[n] = carry;
}

__global__ void k_scatter(const int* __restrict__ src, const int* __restrict__ dst,
                          int* __restrict__ cursor, int* __restrict__ srcs, int e_cnt) {
    int e = blockIdx.x*256 + threadIdx.x;
    if (e < e_cnt) {
        int d = dst[e];
        int pos = atomicAdd(&cursor[d], 1);
        srcs[pos] = src[e];
    }
}

// GCN aggregation: g[i] = sum_{e in CSR[i]} p[src]*dinv[i]*dinv[src] + p[i]*dinv[i]^2 + b
// one warp per node, float4 lanes cover 128 cols
__global__ void k_aggregate(const float* __restrict__ p, float* __restrict__ g,
                            const float* __restrict__ dinv,
                            const int* __restrict__ rowptr, const int* __restrict__ srcs,
                            const float* __restrict__ bgcn, int n) {
    int warp = (blockIdx.x*blockDim.x + threadIdx.x) >> 5;
    int lane = threadIdx.x & 31;
    if (warp >= n) return;
    int i = warp;
    float di = dinv[i];
    float4 ps = ((const float4*)(p + (size_t)i*DLAT))[lane];
    float sn = di*di;
    float4 acc;
    acc.x = ps.x*sn; acc.y = ps.y*sn; acc.z = ps.z*sn; acc.w = ps.w*sn;
    int beg = rowptr[i], end = rowptr[i+1];
    for (int e = beg; e < end; e++) {
        int s = srcs[e];
        float w = di * dinv[s];
        float4 v = ((const float4*)(p + (size_t)s*DLAT))[lane];
        acc.x += v.x*w; acc.y += v.y*w; acc.z += v.z*w; acc.w += v.w*w;
    }
    float4 b = ((const float4*)bgcn)[lane];
    acc.x += b.x; acc.y += b.y; acc.z += b.z; acc.w += b.w;
    ((float4*)(g + (size_t)i*DLAT))[lane] = acc;
}

__global__ void k_hup(float* __restrict__ h, const float* __restrict__ mu,
                      const float* __restrict__ sd, const float* __restrict__ eps, int n) {
    int i = blockIdx.x*256 + threadIdx.x;
    if (i < n) h[i] = mu[i] + sd[i]*eps[i];
}

// ---------------- fp32 SGEMM: C = act(A[M,K] @ W[K,Ncol] + b) ----------------
// BM=128, BN=128, BK=32. 256 threads, 8x8 per thread.
template<int ACT>
__global__ __launch_bounds__(256)
void gemm_bias_act(const float* __restrict__ A, const float* __restrict__ W,
                   const float* __restrict__ bias, float* __restrict__ C,
                   int M, int K, int Ncol) {
    const int BM = 128, BN = 128, BK = 32;
    __shared__ float As[BM*BK];   // [m][k], row-major
    __shared__ float Ws[BK*BN];   // [k][n]
    int t  = threadIdx.x;
    int tx = t & 15, ty = t >> 4;
    int rowBase = blockIdx.x * BM;
    int colBase = blockIdx.y * BN;
    float acc[8][8];
    #pragma unroll
    for (int i = 0; i < 8; i++)
        #pragma unroll
        for (int j = 0; j < 8; j++) acc[i][j] = 0.f;

    for (int ko = 0; ko < K; ko += BK) {
        // A tile: 1024 float4, 4 per thread, conflict-free stores
        #pragma unroll
        for (int r = 0; r < 4; r++) {
            int pos = t + r*256;
            int m  = pos >> 3;
            int c4 = pos & 7;
            int grow = rowBase + m;
            float4 v = make_float4(0.f,0.f,0.f,0.f);
            if (grow < M) v = *(const float4*)(A + (size_t)grow*K + ko + c4*4);
            *(float4*)(As + m*BK + c4*4) = v;
        }
        // W tile
        #pragma unroll
        for (int r = 0; r < 4; r++) {
            int pos = t + r*256;
            int kk = pos >> 5;
            int c4 = pos & 31;
            int gcol = colBase + c4*4;
            float4 v = make_float4(0.f,0.f,0.f,0.f);
            if (gcol < Ncol) v = *(const float4*)(W + (size_t)(ko+kk)*Ncol + gcol);
            *(float4*)(Ws + kk*BN + c4*4) = v;
        }
        __syncthreads();
        #pragma unroll
        for (int kk = 0; kk < BK; kk++) {
            float a[8], b[8];
            #pragma unroll
            for (int i = 0; i < 8; i++) a[i] = As[(ty*8+i)*BK + kk];  // broadcast LDS
            *(float4*)(b)   = *(const float4*)(Ws + kk*BN + tx*8);
            *(float4*)(b+4) = *(const float4*)(Ws + kk*BN + tx*8 + 4);
            #pragma unroll
            for (int i = 0; i < 8; i++)
                #pragma unroll
                for (int j = 0; j < 8; j++)
                    acc[i][j] += a[i]*b[j];
        }
        __syncthreads();
    }

    float bb[8];
    #pragma unroll
    for (int j = 0; j < 8; j++) {
        int gcol = colBase + tx*8 + j;
        bb[j] = (bias != nullptr && gcol < Ncol) ? bias[gcol] : 0.f;
    }
    int gcol0 = colBase + tx*8;
    bool fullc = (gcol0 + 8 <= Ncol);
    #pragma unroll
    for (int i = 0; i < 8; i++) {
        int grow = rowBase + ty*8 + i;
        if (grow >= M) continue;
        float v[8];
        #pragma unroll
        for (int j = 0; j < 8; j++) {
            float x = acc[i][j] + bb[j];
            if (ACT == 1)      x = 1.f/(1.f + __expf(-x));
            else if (ACT == 2) x = fmaxf(x, 0.f);
            else if (ACT == 3) { float z = x - 5.f; x = fmaxf(z,0.f) + log1pf(__expf(-fabsf(z))); }
            v[j] = x;
        }
        if (fullc) {
            *(float4*)(C + (size_t)grow*Ncol + gcol0)     = *(float4*)(v);
            *(float4*)(C + (size_t)grow*Ncol + gcol0 + 4) = *(float4*)(v+4);
        } else {
            #pragma unroll
            for (int j = 0; j < 8; j++)
                if (gcol0 + j < Ncol) C[(size_t)grow*Ncol + gcol0 + j] = v[j];
        }
    }
}

// ---------------- fused decoder tail: [N,64] -> relu32 -> relu16 -> sigmoid10 -> pool ----
__global__ __launch_bounds__(256)
void k_dec_tail(const float* __restrict__ D, const float* __restrict__ W3,
                const float* __restrict__ b3, const float* __restrict__ W4,
                const float* __restrict__ b4, const float* __restrict__ Wo,
                const float* __restrict__ bo, const int* __restrict__ batch,
                float* __restrict__ gsum, int* __restrict__ gcnt, int n) {
    __shared__ float sW3[64*32], sW4[32*16], sWo[16*10];
    __shared__ float sb3[32], sb4[16], sbo[10];
    __shared__ float srow[8][64];
    int t = threadIdx.x;
    for (int i = t; i < 64*32; i += 256) sW3[i] = W3[i];
    for (int i = t; i < 32*16; i += 256) sW4[i] = W4[i];
    if (t < 160) sWo[t] = Wo[t];
    if (t < 32)  sb3[t] = b3[t];
    if (t < 16)  sb4[t] = b4[t];
    if (t < 10)  sbo[t] = bo[t];
    __syncthreads();
    int warp = t >> 5, lane = t & 31;
    int row = blockIdx.x*8 + warp;
    if (row >= n) return;
    srow[warp][lane]      = D[(size_t)row*64 + lane];
    srow[warp][lane + 32] = D[(size_t)row*64 + lane + 32];
    __syncwarp();
    float acc = sb3[lane];
    #pragma unroll 8
    for (int k = 0; k < 64; k++) acc += srow[warp][k]*sW3[k*32 + lane];
    float h3 = fmaxf(acc, 0.f);
    float acc4 = (lane < 16) ? sb4[lane] : 0.f;
    #pragma unroll
    for (int k = 0; k < 32; k++) {
        float a = __shfl_sync(0xffffffffu, h3, k);
        if (lane < 16) acc4 += a*sW4[k*16 + lane];
    }
    float h4 = fmaxf(acc4, 0.f);
    float acco = (lane < 10) ? sbo[lane] : 0.f;
    #pragma unroll
    for (int k = 0; k < 16; k++) {
        float a = __shfl_sync(0xffffffffu, h4, k);
        if (lane < 10) acco += a*sWo[k*10 + lane];
    }
    int b = batch[row];
    if (lane < 10) {
        float v = 1.f/(1.f + __expf(-acco));
        atomicAdd(&gsum[b*DOUTD + lane], v);
    }
    if (lane == 0) atomicAdd(&gcnt[b], 1);
}

__global__ void k_finalize(const float* __restrict__ gsum, const int* __restrict__ gcnt,
                           const float* __restrict__ y, float* __restrict__ out) {
    int i = blockIdx.x*256 + threadIdx.x;
    if (i < GG*DOUTD) {
        int gi = i / DOUTD;
        float c = (float)gcnt[gi];
        out[O_YPRED + i] = gsum[i] / fmaxf(c, 1.f);
        out[O_Y + i]     = y[i];
    }
}

// ---------------- host ----------------
static void launch_gemm(int act, const float* A, const float* W, const float* b,
                        float* C, int M, int K, int Ncol) {
    dim3 grid((M + 127)/128, (Ncol + 127)/128);
    switch (act) {
        case 0: gemm_bias_act<0><<<grid, 256>>>(A, W, b, C, M, K, Ncol); break;
        case 1: gemm_bias_act<1><<<grid, 256>>>(A, W, b, C, M, K, Ncol); break;
        case 2: gemm_bias_act<2><<<grid, 256>>>(A, W, b, C, M, K, Ncol); break;
        case 3: gemm_bias_act<3><<<grid, 256>>>(A, W, b, C, M, K, Ncol); break;
    }
}

extern "C" void kernel_launch(void* const* d_in, const int* in_sizes, int n_in,
                              void* d_out, int out_size) {
    const float* x     = (const float*)d_in[0];
    const int*   eidx  = (const int*)  d_in[1];
    const int*   batch = (const int*)  d_in[2];
    const float* y     = (const float*)d_in[3];
    const float* eps   = (const float*)d_in[4];
    const float* W_in  = (const float*)d_in[5];
    const float* b_in  = (const float*)d_in[6];
    const float* W_gcn = (const float*)d_in[7];
    const float* b_gcn = (const float*)d_in[8];
    const float* W_enc = (const float*)d_in[9];
    const float* b_enc = (const float*)d_in[10];
    const float* W_mu  = (const float*)d_in[11];
    const float* b_mu  = (const float*)d_in[12];
    const float* W_std = (const float*)d_in[13];
    const float* b_std = (const float*)d_in[14];
    const float* Wd0 = (const float*)d_in[15]; const float* bd0 = (const float*)d_in[16];
    const float* Wd1 = (const float*)d_in[17]; const float* bd1 = (const float*)d_in[18];
    const float* Wd2 = (const float*)d_in[19]; const float* bd2 = (const float*)d_in[20];
    const float* Wd3 = (const float*)d_in[21]; const float* bd3 = (const float*)d_in[22];
    const float* Wd4 = (const float*)d_in[23]; const float* bd4 = (const float*)d_in[24];
    const float* Wo  = (const float*)d_in[25]; const float* bo  = (const float*)d_in[26];
    float* out = (float*)d_out;

    const int* e_src = eidx;
    const int* e_dst = eidx + EE;

    void* pv;
    cudaGetSymbolAddress(&pv, s_degi);   int*   degi   = (int*)pv;
    cudaGetSymbolAddress(&pv, s_dinv);   float* dinv   = (float*)pv;
    cudaGetSymbolAddress(&pv, s_rowptr); int*   rowptr = (int*)pv;
    cudaGetSymbolAddress(&pv, s_cursor); int*   cursor = (int*)pv;
    cudaGetSymbolAddress(&pv, s_srcs);   int*   srcs   = (int*)pv;
    cudaGetSymbolAddress(&pv, s_h);      float* h      = (float*)pv;
    cudaGetSymbolAddress(&pv, s_p);      float* p      = (float*)pv;
    cudaGetSymbolAddress(&pv, s_g);      float* g      = (float*)pv;
    cudaGetSymbolAddress(&pv, s_t);      float* tbuf   = (float*)pv;
    cudaGetSymbolAddress(&pv, s_dec);    float* dec    = (float*)pv;
    cudaGetSymbolAddress(&pv, s_gsum);   float* gsum   = (float*)pv;
    cudaGetSymbolAddress(&pv, s_gcnt);   int*   gcnt   = (int*)pv;

    float* outMu  = out + O_MU;
    float* outStd = out + O_STD;

    // ---- graph structure (per launch, graph-capturable) ----
    cudaMemsetAsync(degi, 0, NN*sizeof(int), 0);
    cudaMemsetAsync(gsum, 0, GG*DOUTD*sizeof(float), 0);
    cudaMemsetAsync(gcnt, 0, GG*sizeof(int), 0);
    k_count<<<(EE+255)/256, 256>>>(e_dst, degi, EE);
    k_dinv<<<(NN+255)/256, 256>>>(degi, dinv, NN);
    k_scan<<<1, 1024>>>(degi, rowptr, cursor, NN);
    k_scatter<<<(EE+255)/256, 256>>>(e_src, e_dst, cursor, srcs, EE);

    // ---- input layer: h = sigmoid(x @ W_in + b_in) ----
    launch_gemm(1, x, W_in, b_in, h, NN, DIN, DLAT);

    // ---- K hops ----
    for (int hop = 0; hop < KHOPS; hop++) {
        launch_gemm(0, h, W_gcn, nullptr, p, NN, DLAT, DLAT);
        k_aggregate<<<(NN*32 + 255)/256, 256>>>(p, g, dinv, rowptr, srcs, b_gcn, NN);
        float* cur = g; float* other = tbuf;
        for (int j = 0; j < 5; j++) {
            launch_gemm(1, cur, W_enc + (size_t)j*DLAT*DLAT, b_enc + j*DLAT, other, NN, DLAT, DLAT);
            float* tmp = cur; cur = other; other = tmp;
        }
        launch_gemm(0, cur, W_mu,  b_mu,  outMu,  NN, DLAT, DLAT);
        launch_gemm(3, cur, W_std, b_std, outStd, NN, DLAT, DLAT);
        k_hup<<<((int)((size_t)NN*DLAT) + 255)/256, 256>>>(h, outMu, outStd,
                                                           eps + (size_t)hop*NN*DLAT, NN*DLAT);
    }

    // ---- decoder ----
    launch_gemm(2, h,   Wd0, bd0, dec,  NN, DLAT, 256);
    launch_gemm(2, dec, Wd1, bd1, g,    NN, 256, 128);
    launch_gemm(2, g,   Wd2, bd2, tbuf, NN, 128, 64);
    k_dec_tail<<<(NN+7)/8, 256>>>(tbuf, Wd3, bd3, Wd4, bd4, Wo, bo, batch, gsum, gcnt, NN);
    k_finalize<<<(GG*DOUTD + 255)/256, 256>>>(gsum, gcnt, y, out);
}

// round 4
// speedup vs baseline: 1.3160x; 1.3160x over previous
#include <cuda_runtime.h>
#include <cuda_bf16.h>
#include <cstdint>
#include <math.h>

#define NN    50000
#define EE    800000
#define DIN   32
#define DLAT  128
#define DOUTD 10
#define GG    256
#define KHOPS 3

// Output layout: (y_pred [G,10], mu [N,128], std [N,128], y [G,10]) flattened
#define O_YPRED 0
#define O_MU    (GG*DOUTD)
#define O_STD   (O_MU + (size_t)NN*DLAT)
#define O_Y     (O_STD + (size_t)NN*DLAT)

// ---------------- mma.sync helpers (legal at compute_103 baseline) ----------------
__device__ __forceinline__ uint32_t smem_u32(const void* p) {
    uint32_t a;
    asm("{ .reg .u64 t; cvta.to.shared.u64 t, %1; cvt.u32.u64 %0, t; }" : "=r"(a) : "l"(p));
    return a;
}

#define LDSM4(d0, d1, d2, d3, addr) \
    asm volatile("ldmatrix.sync.aligned.m8n8.x4.shared.b16 {%0,%1,%2,%3}, [%4];" \
        : "=r"(d0), "=r"(d1), "=r"(d2), "=r"(d3) : "r"(addr))

#define MMA16816(d, a, b) \
    asm volatile("mma.sync.aligned.m16n8k16.row.col.f32.bf16.bf16.f32 " \
        "{%0,%1,%2,%3}, {%4,%5,%6,%7}, {%8,%9}, {%0,%1,%2,%3};" \
        : "+f"((d)[0]), "+f"((d)[1]), "+f"((d)[2]), "+f"((d)[3]) \
        : "r"((a)[0]), "r"((a)[1]), "r"((a)[2]), "r"((a)[3]), \
          "r"((b)[0]), "r"((b)[1]))

// ---------------- scratch (__device__ globals, no allocs) ----------------
__device__ int   s_degi[NN];
__device__ float s_dinv[NN];
__device__ int   s_rowptr[NN+1];
__device__ int   s_cursor[NN];
__device__ int   s_srcs[EE];
__device__ float s_h[(size_t)NN*DLAT];
__device__ float s_p[(size_t)NN*DLAT];
__device__ float s_g[(size_t)NN*DLAT];
__device__ float s_t[(size_t)NN*DLAT];
__device__ float s_dec[(size_t)NN*256];
__device__ float s_gsum[GG*DOUTD];
__device__ int   s_gcnt[GG];

// bf16 hi/lo weight pool, layout [N,K] per matrix (transposed; K contiguous = mma col-major B)
#define WOFF_IN     0                      // N=128, K=32  -> 4096
#define WOFF_GCN    4096                   // 128x128      -> 16384
#define WOFF_ENC    20480                  // 5 x 16384
#define WOFF_MUSTD  102400                 // fused interleaved N=256, K=128 -> 32768
#define WOFF_D0     135168                 // N=256, K=128 -> 32768
#define WOFF_D1     167936                 // N=128, K=256 -> 32768
#define WOFF_D2     200704                 // N=64,  K=128 -> 8192
#define WPOOL_SZ    208896
__device__ __nv_bfloat16 s_Whi[WPOOL_SZ];
__device__ __nv_bfloat16 s_Wlo[WPOOL_SZ];

// ---------------- graph-structure kernels ----------------
__global__ void k_count(const int* __restrict__ dst, int* __restrict__ degi, int e_cnt) {
    int e = blockIdx.x*256 + threadIdx.x;
    if (e < e_cnt) atomicAdd(&degi[dst[e]], 1);
}

__global__ void k_dinv(const int* __restrict__ degi, float* __restrict__ dinv, int n) {
    int i = blockIdx.x*256 + threadIdx.x;
    if (i < n) dinv[i] = rsqrtf((float)degi[i] + 1.0f);
}

// single-block scan, warp-shuffle based
__global__ void k_scan(const int* __restrict__ cnt, int* __restrict__ rowptr,
                       int* __restrict__ cursor, int n) {
    __shared__ int warpsum[32];
    __shared__ int carrySh;
    int t = threadIdx.x, lane = t & 31, w = t >> 5;
    if (t == 0) carrySh = 0;
    __syncthreads();
    for (int base = 0; base < n; base += 1024) {
        int i = base + t;
        int v = (i < n) ? cnt[i] : 0;
        int s = v;
        #pragma unroll
        for (int o = 1; o < 32; o <<= 1) { int u = __shfl_up_sync(~0u, s, o); if (lane >= o) s += u; }
        if (lane == 31) warpsum[w] = s;
        __syncthreads();
        if (w == 0) {
            int ws = warpsum[lane];
            #pragma unroll
            for (int o = 1; o < 32; o <<= 1) { int u = __shfl_up_sync(~0u, ws, o); if (lane >= o) ws += u; }
            warpsum[lane] = ws;
        }
        __syncthreads();
        int excl = carrySh + (w > 0 ? warpsum[w-1] : 0) + s - v;
        if (i < n) { rowptr[i] = excl; cursor[i] = excl; }
        __syncthreads();
        if (t == 0) carrySh += warpsum[31];
        __syncthreads();
    }
    if (threadIdx.x == 0) rowptr[n] = carrySh;
}

__global__ void k_scatter(const int* __restrict__ src, const int* __restrict__ dst,
                          int* __restrict__ cursor, int* __restrict__ srcs, int e_cnt) {
    int e = blockIdx.x*256 + threadIdx.x;
    if (e < e_cnt) {
        int d = dst[e];
        int pos = atomicAdd(&cursor[d], 1);
        srcs[pos] = src[e];
    }
}

// ---------------- GCN aggregation (one warp per node) ----------------
__global__ void k_aggregate(const float* __restrict__ p, float* __restrict__ g,
                            const float* __restrict__ dinv,
                            const int* __restrict__ rowptr, const int* __restrict__ srcs,
                            const float* __restrict__ bgcn, int n) {
    int warp = (blockIdx.x*blockDim.x + threadIdx.x) >> 5;
    int lane = threadIdx.x & 31;
    if (warp >= n) return;
    int i = warp;
    float di = dinv[i];
    float4 ps = ((const float4*)(p + (size_t)i*DLAT))[lane];
    float sn = di*di;
    float4 acc;
    acc.x = ps.x*sn; acc.y = ps.y*sn; acc.z = ps.z*sn; acc.w = ps.w*sn;
    int beg = rowptr[i], end = rowptr[i+1];
    for (int e = beg; e < end; e++) {
        int s = srcs[e];
        float w = di * dinv[s];
        float4 v = ((const float4*)(p + (size_t)s*DLAT))[lane];
        acc.x += v.x*w; acc.y += v.y*w; acc.z += v.z*w; acc.w += v.w*w;
    }
    float4 b = ((const float4*)bgcn)[lane];
    acc.x += b.x; acc.y += b.y; acc.z += b.z; acc.w += b.w;
    ((float4*)(g + (size_t)i*DLAT))[lane] = acc;
}

// ---------------- weight conversion ----------------
// W[K,N] fp32 -> B[N,K] bf16 hi/lo
__global__ void k_wconv(const float* __restrict__ W, __nv_bfloat16* __restrict__ Bhi,
                        __nv_bfloat16* __restrict__ Blo, int K, int N) {
    int tid = blockIdx.x*256 + threadIdx.x;
    if (tid >= N*K) return;
    int n = tid / K, k = tid - n*K;
    float w = W[(size_t)k*N + n];
    __nv_bfloat16 hi = __float2bfloat16_rn(w);
    float r = w - __bfloat162float(hi);
    Bhi[tid] = hi;
    Blo[tid] = __float2bfloat16_rn(r);
}

// fused mu/std: rows interleaved (2j = W_mu col j, 2j+1 = W_std col j), K=128
__global__ void k_wconv_fused(const float* __restrict__ Wmu, const float* __restrict__ Wstd,
                              __nv_bfloat16* __restrict__ Bhi, __nv_bfloat16* __restrict__ Blo) {
    int tid = blockIdx.x*256 + threadIdx.x;
    if (tid >= 256*DLAT) return;
    int n = tid >> 7, k = tid & 127;
    int j = n >> 1;
    float w = (n & 1) ? Wstd[(size_t)k*DLAT + j] : Wmu[(size_t)k*DLAT + j];
    __nv_bfloat16 hi = __float2bfloat16_rn(w);
    float r = w - __bfloat162float(hi);
    Bhi[tid] = hi;
    Blo[tid] = __float2bfloat16_rn(r);
}

// ---------------- bf16-split tensor-core GEMM (mma.sync m16n8k16) ----------------
// C = act(A[M,K] @ W[K,N] + bias). Tile 128x128, BK=64, 8 warps (2M x 4N), warp 64x32.
// 3-product split: Ahi*Bhi + Alo*Bhi + Ahi*Blo, fp32 accumulate.
// ACT: 0 none, 1 sigmoid, 2 relu, 4 fused mu/std epilogue (N=256 interleaved).
template<int ACT>
__global__ __launch_bounds__(256)
void tc_gemm(const float* __restrict__ A,
             const __nv_bfloat16* __restrict__ Bhi_g,
             const __nv_bfloat16* __restrict__ Blo_g,
             const float* __restrict__ bias,
             const float* __restrict__ bias2,
             const float* __restrict__ epsp,
             float* __restrict__ C,
             float* __restrict__ C2,
             float* __restrict__ C3,
             int M, int K, int Nglobal) {
    constexpr int BM = 128, BN = 128, BK = 64, SA = 72; // 8-bf16 pad: ldmatrix conflict-free
    extern __shared__ __nv_bfloat16 sm[];
    __nv_bfloat16* Ah = sm;
    __nv_bfloat16* Al = Ah + BM*SA;
    __nv_bfloat16* Bh = Al + BM*SA;
    __nv_bfloat16* Bl = Bh + BN*SA;

    int t = threadIdx.x, lane = t & 31, warp = t >> 5;
    int wm = warp & 1, wn = warp >> 1;            // 2 x 4 warp grid
    int rowBase = blockIdx.x * BM, colBase = blockIdx.y * BN;
    int wrow = wm * 64, wcol = wn * 32;

    float acc[4][4][4];
    #pragma unroll
    for (int i = 0; i < 4; i++)
        #pragma unroll
        for (int j = 0; j < 4; j++)
            #pragma unroll
            for (int q = 0; q < 4; q++) acc[i][j][q] = 0.f;

    uint32_t aHi = smem_u32(Ah), aLo = smem_u32(Al);
    uint32_t bHi = smem_u32(Bh), bLo = smem_u32(Bl);

    // ldmatrix lane addressing
    int aRow  = wrow + (lane & 15);               // rows 0-15 of the m16 tile
    int aColO = (lane >> 4) << 3;                 // k 0 / +8
    int bN    = wcol + ((lane >> 4) << 3) + (lane & 7);  // n rows for 2 ntiles
    int bKO   = ((lane >> 3) & 1) << 3;           // k 0 / +8

    for (int ko = 0; ko < K; ko += BK) {
        // ---- A tile: fp32 -> bf16 hi/lo split, [row][k] ----
        #pragma unroll
        for (int r = 0; r < 8; r++) {
            int pos = t + r*256;                  // 2048 float4 slots
            int row = pos >> 4, c4 = (pos & 15) << 2;
            float4 v = make_float4(0.f, 0.f, 0.f, 0.f);
            int gr = rowBase + row, gc = ko + c4;
            if (gr < M && gc < K) v = *(const float4*)(A + (size_t)gr*K + gc);
            __nv_bfloat162 h01 = __floats2bfloat162_rn(v.x, v.y);
            __nv_bfloat162 h23 = __floats2bfloat162_rn(v.z, v.w);
            float r0 = v.x - __bfloat162float(h01.x);
            float r1 = v.y - __bfloat162float(h01.y);
            float r2 = v.z - __bfloat162float(h23.x);
            float r3 = v.w - __bfloat162float(h23.y);
            __nv_bfloat162 l01 = __floats2bfloat162_rn(r0, r1);
            __nv_bfloat162 l23 = __floats2bfloat162_rn(r2, r3);
            uint2 uh, ul;
            uh.x = *reinterpret_cast<uint32_t*>(&h01); uh.y = *reinterpret_cast<uint32_t*>(&h23);
            ul.x = *reinterpret_cast<uint32_t*>(&l01); ul.y = *reinterpret_cast<uint32_t*>(&l23);
            *(uint2*)(Ah + row*SA + c4) = uh;
            *(uint2*)(Al + row*SA + c4) = ul;
        }
        // ---- B tile: preconverted bf16 hi/lo, [n][k] ----
        #pragma unroll
        for (int r = 0; r < 8; r++) {
            int pos = t + r*256;
            int n = pos >> 4, c4 = (pos & 15) << 2;
            uint2 vh = make_uint2(0, 0), vl = make_uint2(0, 0);
            int gn = colBase + n, gc = ko + c4;
            if (gn < Nglobal && gc < K) {
                size_t off = (size_t)gn*K + gc;
                vh = *(const uint2*)(Bhi_g + off);
                vl = *(const uint2*)(Blo_g + off);
            }
            *(uint2*)(Bh + n*SA + c4) = vh;
            *(uint2*)(Bl + n*SA + c4) = vl;
        }
        __syncthreads();

        #pragma unroll
        for (int ks = 0; ks < BK/16; ks++) {
            uint32_t ah[4][4], al[4][4], bh[4][2], bl[4][2];
            #pragma unroll
            for (int mi = 0; mi < 4; mi++) {
                uint32_t off = (uint32_t)(((aRow + mi*16)*SA + ks*16 + aColO) * 2);
                LDSM4(ah[mi][0], ah[mi][1], ah[mi][2], ah[mi][3], aHi + off);
                LDSM4(al[mi][0], al[mi][1], al[mi][2], al[mi][3], aLo + off);
            }
            #pragma unroll
            for (int np = 0; np < 2; np++) {
                uint32_t off = (uint32_t)(((bN + np*16)*SA + ks*16 + bKO) * 2);
                uint32_t r0, r1, r2, r3;
                LDSM4(r0, r1, r2, r3, bHi + off);
                bh[np*2][0] = r0; bh[np*2][1] = r1; bh[np*2+1][0] = r2; bh[np*2+1][1] = r3;
                LDSM4(r0, r1, r2, r3, bLo + off);
                bl[np*2][0] = r0; bl[np*2][1] = r1; bl[np*2+1][0] = r2; bl[np*2+1][1] = r3;
            }
            #pragma unroll
            for (int mi = 0; mi < 4; mi++)
                #pragma unroll
                for (int ni = 0; ni < 4; ni++) {
                    MMA16816(acc[mi][ni], ah[mi], bh[ni]);
                    MMA16816(acc[mi][ni], al[mi], bh[ni]);
                    MMA16816(acc[mi][ni], ah[mi], bl[ni]);
                }
        }
        __syncthreads();
    }

    // ---- epilogue ----
    int r0base = rowBase + wrow + (lane >> 2);
    int c0base = colBase + wcol + (lane & 3)*2;
    #pragma unroll
    for (int mi = 0; mi < 4; mi++) {
        int row = r0base + mi*16;
        #pragma unroll
        for (int ni = 0; ni < 4; ni++) {
            int col = c0base + ni*8;
            float* cc = acc[mi][ni];
            if (ACT == 4) {
                int j = col >> 1;
                #pragma unroll
                for (int half = 0; half < 2; half++) {
                    int rr = row + half*8;
                    if (rr < M) {
                        float mu = cc[half*2] + bias[j];
                        float z  = cc[half*2+1] + bias2[j] - 5.f;
                        float sp = fmaxf(z, 0.f) + log1pf(__expf(-fabsf(z)));
                        size_t o = (size_t)rr*DLAT + j;
                        C[o]  = mu;
                        C2[o] = sp;
                        C3[o] = mu + sp*epsp[o];
                    }
                }
            } else {
                if (col < Nglobal) {
                    float b0 = bias ? bias[col]   : 0.f;
                    float b1 = bias ? bias[col+1] : 0.f;
                    #pragma unroll
                    for (int half = 0; half < 2; half++) {
                        int rr = row + half*8;
                        if (rr < M) {
                            float x0 = cc[half*2] + b0;
                            float x1 = cc[half*2+1] + b1;
                            if (ACT == 1) { x0 = 1.f/(1.f + __expf(-x0)); x1 = 1.f/(1.f + __expf(-x1)); }
                            else if (ACT == 2) { x0 = fmaxf(x0, 0.f); x1 = fmaxf(x1, 0.f); }
                            float2 vv = make_float2(x0, x1);
                            *(float2*)(C + (size_t)rr*Nglobal + col) = vv;
                        }
                    }
                }
            }
        }
    }
}

// ---------------- fused decoder tail: [N,64] -> relu32 -> relu16 -> sigmoid10 -> pool ----
__global__ __launch_bounds__(256)
void k_dec_tail(const float* __restrict__ D, const float* __restrict__ W3,
                const float* __restrict__ b3, const float* __restrict__ W4,
                const float* __restrict__ b4, const float* __restrict__ Wo,
                const float* __restrict__ bo, const int* __restrict__ batch,
                float* __restrict__ gsum, int* __restrict__ gcnt, int n) {
    __shared__ float sW3[64*32], sW4[32*16], sWo[16*10];
    __shared__ float sb3[32], sb4[16], sbo[10];
    __shared__ float srow[8][64];
    int t = threadIdx.x;
    for (int i = t; i < 64*32; i += 256) sW3[i] = W3[i];
    for (int i = t; i < 32*16; i += 256) sW4[i] = W4[i];
    if (t < 160) sWo[t] = Wo[t];
    if (t < 32)  sb3[t] = b3[t];
    if (t < 16)  sb4[t] = b4[t];
    if (t < 10)  sbo[t] = bo[t];
    __syncthreads();
    int warp = t >> 5, lane = t & 31;
    int row = blockIdx.x*8 + warp;
    if (row >= n) return;
    srow[warp][lane]      = D[(size_t)row*64 + lane];
    srow[warp][lane + 32] = D[(size_t)row*64 + lane + 32];
    __syncwarp();
    float acc = sb3[lane];
    #pragma unroll 8
    for (int k = 0; k < 64; k++) acc += srow[warp][k]*sW3[k*32 + lane];
    float h3 = fmaxf(acc, 0.f);
    float acc4 = (lane < 16) ? sb4[lane] : 0.f;
    #pragma unroll
    for (int k = 0; k < 32; k++) {
        float a = __shfl_sync(0xffffffffu, h3, k);
        if (lane < 16) acc4 += a*sW4[k*16 + lane];
    }
    float h4 = fmaxf(acc4, 0.f);
    float acco = (lane < 10) ? sbo[lane] : 0.f;
    #pragma unroll
    for (int k = 0; k < 16; k++) {
        float a = __shfl_sync(0xffffffffu, h4, k);
        if (lane < 10) acco += a*sWo[k*10 + lane];
    }
    int b = batch[row];
    if (lane < 10) {
        float v = 1.f/(1.f + __expf(-acco));
        atomicAdd(&gsum[b*DOUTD + lane], v);
    }
    if (lane == 0) atomicAdd(&gcnt[b], 1);
}

__global__ void k_finalize(const float* __restrict__ gsum, const int* __restrict__ gcnt,
                           const float* __restrict__ y, float* __restrict__ out) {
    int i = blockIdx.x*256 + threadIdx.x;
    if (i < GG*DOUTD) {
        int gi = i / DOUTD;
        float c = (float)gcnt[gi];
        out[O_YPRED + i] = gsum[i] / fmaxf(c, 1.f);
        out[O_Y + i]     = y[i];
    }
}

// ---------------- host ----------------
static const __nv_bfloat16* g_whi;
static const __nv_bfloat16* g_wlo;
static constexpr int TC_SMEM = 4 * 128 * 72 * 2;   // 73728 bytes

static void launch_tc(int act, const float* A, int woff,
                      const float* b, const float* b2, const float* epsp,
                      float* C, float* C2, float* C3, int M, int K, int Ncol) {
    const __nv_bfloat16* bh = g_whi + woff;
    const __nv_bfloat16* bl = g_wlo + woff;
    dim3 grid((M + 127)/128, (Ncol + 127)/128);
    switch (act) {
    case 0:
        cudaFuncSetAttribute(tc_gemm<0>, cudaFuncAttributeMaxDynamicSharedMemorySize, TC_SMEM);
        tc_gemm<0><<<grid, 256, TC_SMEM>>>(A, bh, bl, b, b2, epsp, C, C2, C3, M, K, Ncol); break;
    case 1:
        cudaFuncSetAttribute(tc_gemm<1>, cudaFuncAttributeMaxDynamicSharedMemorySize, TC_SMEM);
        tc_gemm<1><<<grid, 256, TC_SMEM>>>(A, bh, bl, b, b2, epsp, C, C2, C3, M, K, Ncol); break;
    case 2:
        cudaFuncSetAttribute(tc_gemm<2>, cudaFuncAttributeMaxDynamicSharedMemorySize, TC_SMEM);
        tc_gemm<2><<<grid, 256, TC_SMEM>>>(A, bh, bl, b, b2, epsp, C, C2, C3, M, K, Ncol); break;
    case 4:
        cudaFuncSetAttribute(tc_gemm<4>, cudaFuncAttributeMaxDynamicSharedMemorySize, TC_SMEM);
        tc_gemm<4><<<grid, 256, TC_SMEM>>>(A, bh, bl, b, b2, epsp, C, C2, C3, M, K, Ncol); break;
    }
}

extern "C" void kernel_launch(void* const* d_in, const int* in_sizes, int n_in,
                              void* d_out, int out_size) {
    const float* x     = (const float*)d_in[0];
    const int*   eidx  = (const int*)  d_in[1];
    const int*   batch = (const int*)  d_in[2];
    const float* y     = (const float*)d_in[3];
    const float* eps   = (const float*)d_in[4];
    const float* W_in  = (const float*)d_in[5];
    const float* b_in  = (const float*)d_in[6];
    const float* W_gcn = (const float*)d_in[7];
    const float* b_gcn = (const float*)d_in[8];
    const float* W_enc = (const float*)d_in[9];
    const float* b_enc = (const float*)d_in[10];
    const float* W_mu  = (const float*)d_in[11];
    const float* b_mu  = (const float*)d_in[12];
    const float* W_std = (const float*)d_in[13];
    const float* b_std = (const float*)d_in[14];
    const float* Wd0 = (const float*)d_in[15]; const float* bd0 = (const float*)d_in[16];
    const float* Wd1 = (const float*)d_in[17]; const float* bd1 = (const float*)d_in[18];
    const float* Wd2 = (const float*)d_in[19]; const float* bd2 = (const float*)d_in[20];
    const float* Wd3 = (const float*)d_in[21]; const float* bd3 = (const float*)d_in[22];
    const float* Wd4 = (const float*)d_in[23]; const float* bd4 = (const float*)d_in[24];
    const float* Wo  = (const float*)d_in[25]; const float* bo  = (const float*)d_in[26];
    float* out = (float*)d_out;

    const int* e_src = eidx;
    const int* e_dst = eidx + EE;

    void* pv;
    cudaGetSymbolAddress(&pv, s_degi);   int*   degi   = (int*)pv;
    cudaGetSymbolAddress(&pv, s_dinv);   float* dinv   = (float*)pv;
    cudaGetSymbolAddress(&pv, s_rowptr); int*   rowptr = (int*)pv;
    cudaGetSymbolAddress(&pv, s_cursor); int*   cursor = (int*)pv;
    cudaGetSymbolAddress(&pv, s_srcs);   int*   srcs   = (int*)pv;
    cudaGetSymbolAddress(&pv, s_h);      float* h      = (float*)pv;
    cudaGetSymbolAddress(&pv, s_p);      float* p      = (float*)pv;
    cudaGetSymbolAddress(&pv, s_g);      float* g      = (float*)pv;
    cudaGetSymbolAddress(&pv, s_t);      float* tbuf   = (float*)pv;
    cudaGetSymbolAddress(&pv, s_dec);    float* dec    = (float*)pv;
    cudaGetSymbolAddress(&pv, s_gsum);   float* gsum   = (float*)pv;
    cudaGetSymbolAddress(&pv, s_gcnt);   int*   gcnt   = (int*)pv;
    cudaGetSymbolAddress(&pv, s_Whi);    __nv_bfloat16* whi = (__nv_bfloat16*)pv;
    cudaGetSymbolAddress(&pv, s_Wlo);    __nv_bfloat16* wlo = (__nv_bfloat16*)pv;
    g_whi = whi; g_wlo = wlo;

    float* outMu  = out + O_MU;
    float* outStd = out + O_STD;

    // ---- weight conversion (fp32 -> bf16 hi/lo, transposed to [N,K]) ----
    auto wc = [&](const float* W, int woff, int K, int N) {
        k_wconv<<<(N*K + 255)/256, 256>>>(W, whi + woff, wlo + woff, K, N);
    };
    wc(W_in,  WOFF_IN,  DIN,  DLAT);
    wc(W_gcn, WOFF_GCN, DLAT, DLAT);
    for (int j = 0; j < 5; j++)
        wc(W_enc + (size_t)j*DLAT*DLAT, WOFF_ENC + j*DLAT*DLAT, DLAT, DLAT);
    k_wconv_fused<<<(256*DLAT + 255)/256, 256>>>(W_mu, W_std, whi + WOFF_MUSTD, wlo + WOFF_MUSTD);
    wc(Wd0, WOFF_D0, DLAT, 256);
    wc(Wd1, WOFF_D1, 256,  DLAT);
    wc(Wd2, WOFF_D2, DLAT, 64);

    // ---- graph structure ----
    cudaMemsetAsync(degi, 0, NN*sizeof(int), 0);
    cudaMemsetAsync(gsum, 0, GG*DOUTD*sizeof(float), 0);
    cudaMemsetAsync(gcnt, 0, GG*sizeof(int), 0);
    k_count<<<(EE+255)/256, 256>>>(e_dst, degi, EE);
    k_dinv<<<(NN+255)/256, 256>>>(degi, dinv, NN);
    k_scan<<<1, 1024>>>(degi, rowptr, cursor, NN);
    k_scatter<<<(EE+255)/256, 256>>>(e_src, e_dst, cursor, srcs, EE);

    // ---- input layer: h = sigmoid(x @ W_in + b_in) ----
    launch_tc(1, x, WOFF_IN, b_in, nullptr, nullptr, h, nullptr, nullptr, NN, DIN, DLAT);

    // ---- K hops ----
    for (int hop = 0; hop < KHOPS; hop++) {
        launch_tc(0, h, WOFF_GCN, nullptr, nullptr, nullptr, p, nullptr, nullptr, NN, DLAT, DLAT);
        k_aggregate<<<(NN*32 + 255)/256, 256>>>(p, g, dinv, rowptr, srcs, b_gcn, NN);
        float* cur = g; float* other = tbuf;
        for (int j = 0; j < 5; j++) {
            launch_tc(1, cur, WOFF_ENC + j*DLAT*DLAT, b_enc + j*DLAT, nullptr, nullptr,
                      other, nullptr, nullptr, NN, DLAT, DLAT);
            float* tmp = cur; cur = other; other = tmp;
        }
        // fused mu/std/reparam: writes outMu, outStd, and h = mu + softplus*eps
        launch_tc(4, cur, WOFF_MUSTD, b_mu, b_std, eps + (size_t)hop*NN*DLAT,
                  outMu, outStd, h, NN, DLAT, 256);
    }

    // ---- decoder ----
    launch_tc(2, h,   WOFF_D0, bd0, nullptr, nullptr, dec,  nullptr, nullptr, NN, DLAT, 256);
    launch_tc(2, dec, WOFF_D1, bd1, nullptr, nullptr, g,    nullptr, nullptr, NN, 256,  DLAT);
    launch_tc(2, g,   WOFF_D2, bd2, nullptr, nullptr, tbuf, nullptr, nullptr, NN, DLAT, 64);
    k_dec_tail<<<(NN+7)/8, 256>>>(tbuf, Wd3, bd3, Wd4, bd4, Wo, bo, batch, gsum, gcnt, NN);
    k_finalize<<<(GG*DOUTD + 255)/256, 256>>>(gsum, gcnt, y, out);
}

// round 5
// speedup vs baseline: 1.4240x; 1.0820x over previous
#include <cuda_runtime.h>
#include <cuda_bf16.h>
#include <cstdint>
#include <math.h>

#define NN    50000
#define EE    800000
#define DIN   32
#define DLAT  128
#define DOUTD 10
#define GG    256
#define KHOPS 3

// Output layout: (y_pred [G,10], mu [N,128], std [N,128], y [G,10]) flattened
#define O_YPRED 0
#define O_MU    (GG*DOUTD)
#define O_STD   (O_MU + (size_t)NN*DLAT)
#define O_Y     (O_STD + (size_t)NN*DLAT)

// ---------------- PTX helpers (legal at compute_103 baseline) ----------------
__device__ __forceinline__ uint32_t smem_u32(const void* p) {
    uint32_t a;
    asm("{ .reg .u64 t; cvta.to.shared.u64 t, %1; cvt.u32.u64 %0, t; }" : "=r"(a) : "l"(p));
    return a;
}

#define LDSM4(d0, d1, d2, d3, addr) \
    asm volatile("ldmatrix.sync.aligned.m8n8.x4.shared.b16 {%0,%1,%2,%3}, [%4];" \
        : "=r"(d0), "=r"(d1), "=r"(d2), "=r"(d3) : "r"(addr))

#define MMA16816(d, a, b) \
    asm volatile("mma.sync.aligned.m16n8k16.row.col.f32.bf16.bf16.f32 " \
        "{%0,%1,%2,%3}, {%4,%5,%6,%7}, {%8,%9}, {%0,%1,%2,%3};" \
        : "+f"((d)[0]), "+f"((d)[1]), "+f"((d)[2]), "+f"((d)[3]) \
        : "r"((a)[0]), "r"((a)[1]), "r"((a)[2]), "r"((a)[3]), \
          "r"((b)[0]), "r"((b)[1]))

#define CP_ASYNC16(dst, src, sz) \
    asm volatile("cp.async.cg.shared.global [%0], [%1], 16, %2;" \
        :: "r"(dst), "l"(src), "r"(sz))

#define CP_WAIT_ALL() asm volatile("cp.async.wait_all;" ::: "memory")

// ---------------- scratch (__device__ globals, no allocs) ----------------
__device__ int   s_degi[NN];
__device__ float s_dinv[NN];
__device__ int   s_rowptr[NN+1];
__device__ int   s_cursor[NN];
__device__ int   s_srcs[EE];
__device__ float s_h[(size_t)NN*DLAT];
__device__ float s_p[(size_t)NN*DLAT];
__device__ float s_g[(size_t)NN*DLAT];
__device__ float s_t[(size_t)NN*DLAT];
__device__ float s_dec[(size_t)NN*256];
__device__ float s_gsum[GG*DOUTD];
__device__ int   s_gcnt[GG];

// bf16 hi/lo weight pool, layout [N,K] per matrix (transposed; K contiguous)
#define WOFF_IN     0                      // N=128, K=32  -> 4096
#define WOFF_GCN    4096                   // 128x128      -> 16384
#define WOFF_ENC    20480                  // 5 x 16384
#define WOFF_MUSTD  102400                 // interleaved N=256, K=128 -> 32768
#define WOFF_D0     135168                 // N=256, K=128 -> 32768
#define WOFF_D1     167936                 // N=128, K=256 -> 32768
#define WOFF_D2     200704                 // N=64,  K=128 -> 8192
#define WPOOL_SZ    208896
__device__ __align__(16) __nv_bfloat16 s_Whi[WPOOL_SZ];
__device__ __align__(16) __nv_bfloat16 s_Wlo[WPOOL_SZ];

// ---------------- fused weight conversion (1 kernel for all matrices) ----------------
__global__ void k_wconv_all(const float* __restrict__ W_in, const float* __restrict__ W_gcn,
                            const float* __restrict__ W_enc,
                            const float* __restrict__ W_mu, const float* __restrict__ W_std,
                            const float* __restrict__ Wd0, const float* __restrict__ Wd1,
                            const float* __restrict__ Wd2,
                            __nv_bfloat16* __restrict__ Bhi, __nv_bfloat16* __restrict__ Blo) {
    int tid = blockIdx.x*256 + threadIdx.x;
    if (tid >= WPOOL_SZ) return;
    float w;
    if (tid < 4096) {                       // W_in [32,128] -> [128,32]
        int l = tid, n = l >> 5, k = l & 31;
        w = W_in[k*128 + n];
    } else if (tid < 20480) {               // W_gcn [128,128]
        int l = tid - 4096, n = l >> 7, k = l & 127;
        w = W_gcn[k*128 + n];
    } else if (tid < 102400) {              // W_enc [5][128,128]
        int l = tid - 20480, e = l >> 14, r = l & 16383, n = r >> 7, k = r & 127;
        w = W_enc[e*16384 + k*128 + n];
    } else if (tid < 135168) {              // fused mu/std interleaved [256,128]
        int l = tid - 102400, n = l >> 7, k = l & 127, j = n >> 1;
        w = (n & 1) ? W_std[k*128 + j] : W_mu[k*128 + j];
    } else if (tid < 167936) {              // Wd0 [128,256] -> [256,128]
        int l = tid - 135168, n = l >> 7, k = l & 127;
        w = Wd0[k*256 + n];
    } else if (tid < 200704) {              // Wd1 [256,128] -> [128,256]
        int l = tid - 167936, n = l >> 8, k = l & 255;
        w = Wd1[k*128 + n];
    } else {                                // Wd2 [128,64] -> [64,128]
        int l = tid - 200704, n = l >> 7, k = l & 127;
        w = Wd2[k*64 + n];
    }
    __nv_bfloat16 hi = __float2bfloat16_rn(w);
    Bhi[tid] = hi;
    Blo[tid] = __float2bfloat16_rn(w - __bfloat162float(hi));
}

// ---------------- graph-structure kernels ----------------
__global__ void k_count(const int* __restrict__ dst, int* __restrict__ degi, int e_cnt) {
    int e = blockIdx.x*256 + threadIdx.x;
    if (e < e_cnt) atomicAdd(&degi[dst[e]], 1);
}

__global__ void k_dinv(const int* __restrict__ degi, float* __restrict__ dinv, int n) {
    int i = blockIdx.x*256 + threadIdx.x;
    if (i < n) dinv[i] = rsqrtf((float)degi[i] + 1.0f);
}

__global__ void k_scan(const int* __restrict__ cnt, int* __restrict__ rowptr,
                       int* __restrict__ cursor, int n) {
    __shared__ int warpsum[32];
    __shared__ int carrySh;
    int t = threadIdx.x, lane = t & 31, w = t >> 5;
    if (t == 0) carrySh = 0;
    __syncthreads();
    for (int base = 0; base < n; base += 1024) {
        int i = base + t;
        int v = (i < n) ? cnt[i] : 0;
        int s = v;
        #pragma unroll
        for (int o = 1; o < 32; o <<= 1) { int u = __shfl_up_sync(~0u, s, o); if (lane >= o) s += u; }
        if (lane == 31) warpsum[w] = s;
        __syncthreads();
        if (w == 0) {
            int ws = warpsum[lane];
            #pragma unroll
            for (int o = 1; o < 32; o <<= 1) { int u = __shfl_up_sync(~0u, ws, o); if (lane >= o) ws += u; }
            warpsum[lane] = ws;
        }
        __syncthreads();
        int excl = carrySh + (w > 0 ? warpsum[w-1] : 0) + s - v;
        if (i < n) { rowptr[i] = excl; cursor[i] = excl; }
        __syncthreads();
        if (t == 0) carrySh += warpsum[31];
        __syncthreads();
    }
    if (threadIdx.x == 0) rowptr[n] = carrySh;
}

__global__ void k_scatter(const int* __restrict__ src, const int* __restrict__ dst,
                          int* __restrict__ cursor, int* __restrict__ srcs, int e_cnt) {
    int e = blockIdx.x*256 + threadIdx.x;
    if (e < e_cnt) {
        int d = dst[e];
        int pos = atomicAdd(&cursor[d], 1);
        srcs[pos] = src[e];
    }
}

// ---------------- GCN aggregation (one warp per node) ----------------
__global__ void k_aggregate(const float* __restrict__ p, float* __restrict__ g,
                            const float* __restrict__ dinv,
                            const int* __restrict__ rowptr, const int* __restrict__ srcs,
                            const float* __restrict__ bgcn, int n) {
    int warp = (blockIdx.x*blockDim.x + threadIdx.x) >> 5;
    int lane = threadIdx.x & 31;
    if (warp >= n) return;
    int i = warp;
    float di = dinv[i];
    float4 ps = ((const float4*)(p + (size_t)i*DLAT))[lane];
    float sn = di*di;
    float4 acc;
    acc.x = ps.x*sn; acc.y = ps.y*sn; acc.z = ps.z*sn; acc.w = ps.w*sn;
    int beg = rowptr[i], end = rowptr[i+1];
    for (int e = beg; e < end; e++) {
        int s = srcs[e];
        float w = di * dinv[s];
        float4 v = ((const float4*)(p + (size_t)s*DLAT))[lane];
        acc.x += v.x*w; acc.y += v.y*w; acc.z += v.z*w; acc.w += v.w*w;
    }
    float4 b = ((const float4*)bgcn)[lane];
    acc.x += b.x; acc.y += b.y; acc.z += b.z; acc.w += b.w;
    ((float4*)(g + (size_t)i*DLAT))[lane] = acc;
}

// ---------------- bf16-split tensor-core GEMM (mma.sync m16n8k16) ----------------
// Whole 128-K window resident in XOR-swizzled smem (4 ops x 2 chunks x 16KB = 128KB),
// cp.async for pre-converted B, batched LDG + on-the-fly hi/lo split for A,
// ONE __syncthreads per window. Swizzle: 16B-granule g' = g ^ (row&7), 128B rows.
template<int ACT>
__global__ __launch_bounds__(256)
void tc_gemm(const float* __restrict__ A,
             const __nv_bfloat16* __restrict__ Bhi_g,
             const __nv_bfloat16* __restrict__ Blo_g,
             const float* __restrict__ bias,
             const float* __restrict__ bias2,
             const float* __restrict__ epsp,
             float* __restrict__ C,
             float* __restrict__ C2,
             float* __restrict__ C3,
             int M, int K, int Nglobal) {
    constexpr int BM = 128, BN = 128;
    extern __shared__ __nv_bfloat16 sm[];
    // element offsets: each op has 2 chunk-buffers of 8192 elems (16KB)
    __nv_bfloat16* Ah = sm;
    __nv_bfloat16* Al = sm + 16384;
    __nv_bfloat16* Bh = sm + 32768;
    __nv_bfloat16* Bl = sm + 49152;
    uint32_t aHi = smem_u32(Ah), aLo = smem_u32(Al);
    uint32_t bHi = smem_u32(Bh), bLo = smem_u32(Bl);

    int t = threadIdx.x, lane = t & 31, warp = t >> 5;
    int wm = warp & 1, wn = warp >> 1;
    int rowBase = blockIdx.x * BM, colBase = blockIdx.y * BN;
    int wrow = wm * 64, wcol = wn * 32;
    uint32_t l7 = (uint32_t)(lane & 7);

    float acc[4][4][4];
    #pragma unroll
    for (int i = 0; i < 4; i++)
        #pragma unroll
        for (int j = 0; j < 4; j++)
            #pragma unroll
            for (int q = 0; q < 4; q++) acc[i][j][q] = 0.f;

    for (int ko = 0; ko < K; ko += 128) {
        if (ko) __syncthreads();
        int kw = K - ko; if (kw > 128) kw = 128;

        // ---- B: cp.async 16B copies into swizzled smem (4096 total, 16/thread) ----
        #pragma unroll
        for (int r = 0; r < 16; r++) {
            int pos = t + r*256;
            int g = pos & 7, row = (pos >> 3) & 127, chunk = (pos >> 10) & 1, hb = pos >> 11;
            int gk = ko + chunk*64 + g*8;
            int gn = colBase + row;
            bool ok = (gn < Nglobal) && (gk < K);
            const __nv_bfloat16* srcp = (hb ? Blo_g : Bhi_g) + (ok ? ((size_t)gn*K + gk) : 0);
            uint32_t dst = (hb ? bLo : bHi) + (uint32_t)(chunk*16384 + row*128
                          + (((uint32_t)g ^ (uint32_t)(row & 7)) << 4));
            CP_ASYNC16(dst, srcp, ok ? 16u : 0u);
        }

        // ---- A: batched LDG (fp32) -> hi/lo split -> swizzled STS ----
        #pragma unroll
        for (int half = 0; half < 2; half++) {
            float4 av[8];
            #pragma unroll
            for (int r = 0; r < 8; r++) {
                int pos = t + (half*8 + r)*256;
                int row = pos >> 5, c4 = pos & 31;
                int gr = rowBase + row, gc = ko + c4*4;
                av[r] = (gr < M && gc < K) ? *(const float4*)(A + (size_t)gr*K + gc)
                                           : make_float4(0.f, 0.f, 0.f, 0.f);
            }
            #pragma unroll
            for (int r = 0; r < 8; r++) {
                int pos = t + (half*8 + r)*256;
                int row = pos >> 5, c4 = pos & 31;
                int chunk = c4 >> 4, lc4 = c4 & 15;
                float4 v = av[r];
                __nv_bfloat162 h01 = __floats2bfloat162_rn(v.x, v.y);
                __nv_bfloat162 h23 = __floats2bfloat162_rn(v.z, v.w);
                float r0 = v.x - __bfloat162float(h01.x);
                float r1 = v.y - __bfloat162float(h01.y);
                float r2 = v.z - __bfloat162float(h23.x);
                float r3 = v.w - __bfloat162float(h23.y);
                __nv_bfloat162 l01 = __floats2bfloat162_rn(r0, r1);
                __nv_bfloat162 l23 = __floats2bfloat162_rn(r2, r3);
                uint32_t off = (uint32_t)(chunk*16384 + row*128
                              + ((((uint32_t)(lc4 >> 1)) ^ (uint32_t)(row & 7)) << 4)
                              + ((lc4 & 1) << 3));
                uint2 uh, ul;
                uh.x = *reinterpret_cast<uint32_t*>(&h01); uh.y = *reinterpret_cast<uint32_t*>(&h23);
                ul.x = *reinterpret_cast<uint32_t*>(&l01); ul.y = *reinterpret_cast<uint32_t*>(&l23);
                *(uint2*)((char*)Ah + off) = uh;
                *(uint2*)((char*)Al + off) = ul;
            }
        }

        CP_WAIT_ALL();
        __syncthreads();

        // ---- MMA over all ksteps in window ----
        int ksteps = kw >> 4;
        for (int ks = 0; ks < ksteps; ks++) {
            int chunk = ks >> 2, kloc = ks & 3;
            uint32_t choff = (uint32_t)(chunk * 16384);
            uint32_t ah[4][4], al[4][4], bh[4][2], bl[4][2];
            uint32_t gA = ((uint32_t)(kloc*2) + (uint32_t)(lane >> 4)) ^ l7;
            uint32_t gB = ((uint32_t)(kloc*2) + (uint32_t)((lane >> 3) & 1)) ^ l7;
            #pragma unroll
            for (int mi = 0; mi < 4; mi++) {
                uint32_t row = (uint32_t)(wrow + mi*16 + (lane & 15));
                uint32_t off = choff + row*128 + (gA << 4);
                LDSM4(ah[mi][0], ah[mi][1], ah[mi][2], ah[mi][3], aHi + off);
                LDSM4(al[mi][0], al[mi][1], al[mi][2], al[mi][3], aLo + off);
            }
            #pragma unroll
            for (int np = 0; np < 2; np++) {
                uint32_t row = (uint32_t)(wcol + np*16 + ((lane >> 4) << 3) + (lane & 7));
                uint32_t off = choff + row*128 + (gB << 4);
                uint32_t r0, r1, r2, r3;
                LDSM4(r0, r1, r2, r3, bHi + off);
                bh[np*2][0] = r0; bh[np*2][1] = r1; bh[np*2+1][0] = r2; bh[np*2+1][1] = r3;
                LDSM4(r0, r1, r2, r3, bLo + off);
                bl[np*2][0] = r0; bl[np*2][1] = r1; bl[np*2+1][0] = r2; bl[np*2+1][1] = r3;
            }
            #pragma unroll
            for (int mi = 0; mi < 4; mi++)
                #pragma unroll
                for (int ni = 0; ni < 4; ni++) {
                    MMA16816(acc[mi][ni], ah[mi], bh[ni]);
                    MMA16816(acc[mi][ni], al[mi], bh[ni]);
                    MMA16816(acc[mi][ni], ah[mi], bl[ni]);
                }
        }
    }

    // ---- epilogue ----
    int r0base = rowBase + wrow + (lane >> 2);
    int c0base = colBase + wcol + (lane & 3)*2;
    #pragma unroll
    for (int mi = 0; mi < 4; mi++) {
        int row = r0base + mi*16;
        #pragma unroll
        for (int ni = 0; ni < 4; ni++) {
            int col = c0base + ni*8;
            float* cc = acc[mi][ni];
            if (ACT == 4) {
                int j = col >> 1;
                #pragma unroll
                for (int half = 0; half < 2; half++) {
                    int rr = row + half*8;
                    if (rr < M) {
                        float mu = cc[half*2] + bias[j];
                        float z  = cc[half*2+1] + bias2[j] - 5.f;
                        float sp = fmaxf(z, 0.f) + log1pf(__expf(-fabsf(z)));
                        size_t o = (size_t)rr*DLAT + j;
                        C[o]  = mu;
                        C2[o] = sp;
                        C3[o] = mu + sp*epsp[o];
                    }
                }
            } else {
                if (col < Nglobal) {
                    float b0 = bias ? bias[col]   : 0.f;
                    float b1 = bias ? bias[col+1] : 0.f;
                    #pragma unroll
                    for (int half = 0; half < 2; half++) {
                        int rr = row + half*8;
                        if (rr < M) {
                            float x0 = cc[half*2] + b0;
                            float x1 = cc[half*2+1] + b1;
                            if (ACT == 1) { x0 = 1.f/(1.f + __expf(-x0)); x1 = 1.f/(1.f + __expf(-x1)); }
                            else if (ACT == 2) { x0 = fmaxf(x0, 0.f); x1 = fmaxf(x1, 0.f); }
                            float2 vv = make_float2(x0, x1);
                            *(float2*)(C + (size_t)rr*Nglobal + col) = vv;
                        }
                    }
                }
            }
        }
    }
}

// ---------------- fused decoder tail ----------------
__global__ __launch_bounds__(256)
void k_dec_tail(const float* __restrict__ D, const float* __restrict__ W3,
                const float* __restrict__ b3, const float* __restrict__ W4,
                const float* __restrict__ b4, const float* __restrict__ Wo,
                const float* __restrict__ bo, const int* __restrict__ batch,
                float* __restrict__ gsum, int* __restrict__ gcnt, int n) {
    __shared__ float sW3[64*32], sW4[32*16], sWo[16*10];
    __shared__ float sb3[32], sb4[16], sbo[10];
    __shared__ float srow[8][64];
    int t = threadIdx.x;
    for (int i = t; i < 64*32; i += 256) sW3[i] = W3[i];
    for (int i = t; i < 32*16; i += 256) sW4[i] = W4[i];
    if (t < 160) sWo[t] = Wo[t];
    if (t < 32)  sb3[t] = b3[t];
    if (t < 16)  sb4[t] = b4[t];
    if (t < 10)  sbo[t] = bo[t];
    __syncthreads();
    int warp = t >> 5, lane = t & 31;
    int row = blockIdx.x*8 + warp;
    if (row >= n) return;
    srow[warp][lane]      = D[(size_t)row*64 + lane];
    srow[warp][lane + 32] = D[(size_t)row*64 + lane + 32];
    __syncwarp();
    float acc = sb3[lane];
    #pragma unroll 8
    for (int k = 0; k < 64; k++) acc += srow[warp][k]*sW3[k*32 + lane];
    float h3 = fmaxf(acc, 0.f);
    float acc4 = (lane < 16) ? sb4[lane] : 0.f;
    #pragma unroll
    for (int k = 0; k < 32; k++) {
        float a = __shfl_sync(0xffffffffu, h3, k);
        if (lane < 16) acc4 += a*sW4[k*16 + lane];
    }
    float h4 = fmaxf(acc4, 0.f);
    float acco = (lane < 10) ? sbo[lane] : 0.f;
    #pragma unroll
    for (int k = 0; k < 16; k++) {
        float a = __shfl_sync(0xffffffffu, h4, k);
        if (lane < 10) acco += a*sWo[k*10 + lane];
    }
    int b = batch[row];
    if (lane < 10) {
        float v = 1.f/(1.f + __expf(-acco));
        atomicAdd(&gsum[b*DOUTD + lane], v);
    }
    if (lane == 0) atomicAdd(&gcnt[b], 1);
}

__global__ void k_finalize(const float* __restrict__ gsum, const int* __restrict__ gcnt,
                           const float* __restrict__ y, float* __restrict__ out) {
    int i = blockIdx.x*256 + threadIdx.x;
    if (i < GG*DOUTD) {
        int gi = i / DOUTD;
        float c = (float)gcnt[gi];
        out[O_YPRED + i] = gsum[i] / fmaxf(c, 1.f);
        out[O_Y + i]     = y[i];
    }
}

// ---------------- host ----------------
static const __nv_bfloat16* g_whi;
static const __nv_bfloat16* g_wlo;
static constexpr int TC_SMEM = 131072;   // 4 ops x 2 chunks x 16KB

static void launch_tc(int act, const float* A, int woff,
                      const float* b, const float* b2, const float* epsp,
                      float* C, float* C2, float* C3, int M, int K, int Ncol) {
    const __nv_bfloat16* bh = g_whi + woff;
    const __nv_bfloat16* bl = g_wlo + woff;
    dim3 grid((M + 127)/128, (Ncol + 127)/128);
    switch (act) {
    case 0:
        cudaFuncSetAttribute(tc_gemm<0>, cudaFuncAttributeMaxDynamicSharedMemorySize, TC_SMEM);
        tc_gemm<0><<<grid, 256, TC_SMEM>>>(A, bh, bl, b, b2, epsp, C, C2, C3, M, K, Ncol); break;
    case 1:
        cudaFuncSetAttribute(tc_gemm<1>, cudaFuncAttributeMaxDynamicSharedMemorySize, TC_SMEM);
        tc_gemm<1><<<grid, 256, TC_SMEM>>>(A, bh, bl, b, b2, epsp, C, C2, C3, M, K, Ncol); break;
    case 2:
        cudaFuncSetAttribute(tc_gemm<2>, cudaFuncAttributeMaxDynamicSharedMemorySize, TC_SMEM);
        tc_gemm<2><<<grid, 256, TC_SMEM>>>(A, bh, bl, b, b2, epsp, C, C2, C3, M, K, Ncol); break;
    case 4:
        cudaFuncSetAttribute(tc_gemm<4>, cudaFuncAttributeMaxDynamicSharedMemorySize, TC_SMEM);
        tc_gemm<4><<<grid, 256, TC_SMEM>>>(A, bh, bl, b, b2, epsp, C, C2, C3, M, K, Ncol); break;
    }
}

extern "C" void kernel_launch(void* const* d_in, const int* in_sizes, int n_in,
                              void* d_out, int out_size) {
    const float* x     = (const float*)d_in[0];
    const int*   eidx  = (const int*)  d_in[1];
    const int*   batch = (const int*)  d_in[2];
    const float* y     = (const float*)d_in[3];
    const float* eps   = (const float*)d_in[4];
    const float* W_in  = (const float*)d_in[5];
    const float* b_in  = (const float*)d_in[6];
    const float* W_gcn = (const float*)d_in[7];
    const float* b_gcn = (const float*)d_in[8];
    const float* W_enc = (const float*)d_in[9];
    const float* b_enc = (const float*)d_in[10];
    const float* W_mu  = (const float*)d_in[11];
    const float* b_mu  = (const float*)d_in[12];
    const float* W_std = (const float*)d_in[13];
    const float* b_std = (const float*)d_in[14];
    const float* Wd0 = (const float*)d_in[15]; const float* bd0 = (const float*)d_in[16];
    const float* Wd1 = (const float*)d_in[17]; const float* bd1 = (const float*)d_in[18];
    const float* Wd2 = (const float*)d_in[19]; const float* bd2 = (const float*)d_in[20];
    const float* Wd3 = (const float*)d_in[21]; const float* bd3 = (const float*)d_in[22];
    const float* Wd4 = (const float*)d_in[23]; const float* bd4 = (const float*)d_in[24];
    const float* Wo  = (const float*)d_in[25]; const float* bo  = (const float*)d_in[26];
    float* out = (float*)d_out;

    const int* e_src = eidx;
    const int* e_dst = eidx + EE;

    void* pv;
    cudaGetSymbolAddress(&pv, s_degi);   int*   degi   = (int*)pv;
    cudaGetSymbolAddress(&pv, s_dinv);   float* dinv   = (float*)pv;
    cudaGetSymbolAddress(&pv, s_rowptr); int*   rowptr = (int*)pv;
    cudaGetSymbolAddress(&pv, s_cursor); int*   cursor = (int*)pv;
    cudaGetSymbolAddress(&pv, s_srcs);   int*   srcs   = (int*)pv;
    cudaGetSymbolAddress(&pv, s_h);      float* h      = (float*)pv;
    cudaGetSymbolAddress(&pv, s_p);      float* p      = (float*)pv;
    cudaGetSymbolAddress(&pv, s_g);      float* g      = (float*)pv;
    cudaGetSymbolAddress(&pv, s_t);      float* tbuf   = (float*)pv;
    cudaGetSymbolAddress(&pv, s_dec);    float* dec    = (float*)pv;
    cudaGetSymbolAddress(&pv, s_gsum);   float* gsum   = (float*)pv;
    cudaGetSymbolAddress(&pv, s_gcnt);   int*   gcnt   = (int*)pv;
    cudaGetSymbolAddress(&pv, s_Whi);    __nv_bfloat16* whi = (__nv_bfloat16*)pv;
    cudaGetSymbolAddress(&pv, s_Wlo);    __nv_bfloat16* wlo = (__nv_bfloat16*)pv;
    g_whi = whi; g_wlo = wlo;

    float* outMu  = out + O_MU;
    float* outStd = out + O_STD;

    // Launch order arranged so launches #6/#7 are tc_gemm (ncu -s 5 -c 1 capture window).
    // [1] fused weight conversion
    k_wconv_all<<<(WPOOL_SZ + 255)/256, 256>>>(W_in, W_gcn, W_enc, W_mu, W_std,
                                               Wd0, Wd1, Wd2, whi, wlo);
    // [2-4] memsets
    cudaMemsetAsync(degi, 0, NN*sizeof(int), 0);
    cudaMemsetAsync(gsum, 0, GG*DOUTD*sizeof(float), 0);
    cudaMemsetAsync(gcnt, 0, GG*sizeof(int), 0);
    // [5] degree count
    k_count<<<(EE+255)/256, 256>>>(e_dst, degi, EE);
    // [6] input layer: h = sigmoid(x @ W_in + b_in)
    launch_tc(1, x, WOFF_IN, b_in, nullptr, nullptr, h, nullptr, nullptr, NN, DIN, DLAT);
    // [7] hop-0 GCN GEMM  <-- ncu capture target
    launch_tc(0, h, WOFF_GCN, nullptr, nullptr, nullptr, p, nullptr, nullptr, NN, DLAT, DLAT);
    // [8-10] CSR build
    k_dinv<<<(NN+255)/256, 256>>>(degi, dinv, NN);
    k_scan<<<1, 1024>>>(degi, rowptr, cursor, NN);
    k_scatter<<<(EE+255)/256, 256>>>(e_src, e_dst, cursor, srcs, EE);

    // ---- K hops ----
    for (int hop = 0; hop < KHOPS; hop++) {
        if (hop > 0)
            launch_tc(0, h, WOFF_GCN, nullptr, nullptr, nullptr, p, nullptr, nullptr, NN, DLAT, DLAT);
        k_aggregate<<<(NN*32 + 255)/256, 256>>>(p, g, dinv, rowptr, srcs, b_gcn, NN);
        float* cur = g; float* other = tbuf;
        for (int j = 0; j < 5; j++) {
            launch_tc(1, cur, WOFF_ENC + j*DLAT*DLAT, b_enc + j*DLAT, nullptr, nullptr,
                      other, nullptr, nullptr, NN, DLAT, DLAT);
            float* tmp = cur; cur = other; other = tmp;
        }
        launch_tc(4, cur, WOFF_MUSTD, b_mu, b_std, eps + (size_t)hop*NN*DLAT,
                  outMu, outStd, h, NN, DLAT, 256);
    }

    // ---- decoder ----
    launch_tc(2, h,   WOFF_D0, bd0, nullptr, nullptr, dec,  nullptr, nullptr, NN, DLAT, 256);
    launch_tc(2, dec, WOFF_D1, bd1, nullptr, nullptr, g,    nullptr, nullptr, NN, 256,  DLAT);
    launch_tc(2, g,   WOFF_D2, bd2, nullptr, nullptr, tbuf, nullptr, nullptr, NN, DLAT, 64);
    k_dec_tail<<<(NN+7)/8, 256>>>(tbuf, Wd3, bd3, Wd4, bd4, Wo, bo, batch, gsum, gcnt, NN);
    k_finalize<<<(GG*DOUTD + 255)/256, 256>>>(gsum, gcnt, y, out);
}

// round 10
// speedup vs baseline: 1.6973x; 1.1920x over previous
#include <cuda_runtime.h>
#include <cuda_bf16.h>
#include <cstdint>
#include <math.h>

#define NN    50000
#define EE    800000
#define DIN   32
#define DLAT  128
#define DOUTD 10
#define GG    256
#define KHOPS 3

#define O_YPRED 0
#define O_MU    (GG*DOUTD)
#define O_STD   (O_MU + (size_t)NN*DLAT)
#define O_Y     (O_STD + (size_t)NN*DLAT)

// ---------------- PTX helpers (legal at compute_103 baseline) ----------------
__device__ __forceinline__ uint32_t smem_u32(const void* p) {
    uint32_t a;
    asm("{ .reg .u64 t; cvta.to.shared.u64 t, %1; cvt.u32.u64 %0, t; }" : "=r"(a) : "l"(p));
    return a;
}

#define LDSM4(d0, d1, d2, d3, addr) \
    asm volatile("ldmatrix.sync.aligned.m8n8.x4.shared.b16 {%0,%1,%2,%3}, [%4];" \
        : "=r"(d0), "=r"(d1), "=r"(d2), "=r"(d3) : "r"(addr))

#define MMA16816(d, a, b) \
    asm volatile("mma.sync.aligned.m16n8k16.row.col.f32.bf16.bf16.f32 " \
        "{%0,%1,%2,%3}, {%4,%5,%6,%7}, {%8,%9}, {%0,%1,%2,%3};" \
        : "+f"((d)[0]), "+f"((d)[1]), "+f"((d)[2]), "+f"((d)[3]) \
        : "r"((a)[0]), "r"((a)[1]), "r"((a)[2]), "r"((a)[3]), \
          "r"((b)[0]), "r"((b)[1]))

#define CP_ASYNC16(dst, src, sz) \
    asm volatile("cp.async.cg.shared.global [%0], [%1], 16, %2;" \
        :: "r"(dst), "l"(src), "r"(sz))

#define CP_WAIT_ALL() asm volatile("cp.async.wait_all;" ::: "memory")

// ---------------- scratch ----------------
__device__ int   s_degi[NN];
__device__ float s_dinv[NN];
__device__ int   s_rowptr[NN+1];
__device__ int   s_cursor[NN];
__device__ int   s_srcs[EE];
__device__ float s_h[(size_t)NN*DLAT];
__device__ float s_p[(size_t)NN*DLAT];
__device__ float s_g[(size_t)NN*DLAT];
__device__ float s_t[(size_t)NN*DLAT];
__device__ float s_dec[(size_t)NN*256];
__device__ float s_gsum[GG*DOUTD];
__device__ int   s_gcnt[GG];

// bf16 hi/lo weight pool, [N,K] per matrix
#define WOFF_IN     0
#define WOFF_GCN    4096
#define WOFF_ENC    20480
#define WOFF_MUSTD  102400
#define WOFF_D0     135168
#define WOFF_D1     167936
#define WOFF_D2     200704
#define WPOOL_SZ    208896
__device__ __align__(16) __nv_bfloat16 s_Whi[WPOOL_SZ];
__device__ __align__(16) __nv_bfloat16 s_Wlo[WPOOL_SZ];

// ---------------- fused weight conversion ----------------
__global__ void k_wconv_all(const float* __restrict__ W_in, const float* __restrict__ W_gcn,
                            const float* __restrict__ W_enc,
                            const float* __restrict__ W_mu, const float* __restrict__ W_std,
                            const float* __restrict__ Wd0, const float* __restrict__ Wd1,
                            const float* __restrict__ Wd2,
                            __nv_bfloat16* __restrict__ Bhi, __nv_bfloat16* __restrict__ Blo) {
    int tid = blockIdx.x*256 + threadIdx.x;
    if (tid >= WPOOL_SZ) return;
    float w;
    if (tid < 4096) {
        int l = tid, n = l >> 5, k = l & 31;
        w = W_in[k*128 + n];
    } else if (tid < 20480) {
        int l = tid - 4096, n = l >> 7, k = l & 127;
        w = W_gcn[k*128 + n];
    } else if (tid < 102400) {
        int l = tid - 20480, e = l >> 14, r = l & 16383, n = r >> 7, k = r & 127;
        w = W_enc[e*16384 + k*128 + n];
    } else if (tid < 135168) {
        int l = tid - 102400, n = l >> 7, k = l & 127, j = n >> 1;
        w = (n & 1) ? W_std[k*128 + j] : W_mu[k*128 + j];
    } else if (tid < 167936) {
        int l = tid - 135168, n = l >> 7, k = l & 127;
        w = Wd0[k*256 + n];
    } else if (tid < 200704) {
        int l = tid - 167936, n = l >> 8, k = l & 255;
        w = Wd1[k*128 + n];
    } else {
        int l = tid - 200704, n = l >> 7, k = l & 127;
        w = Wd2[k*64 + n];
    }
    __nv_bfloat16 hi = __float2bfloat16_rn(w);
    Bhi[tid] = hi;
    Blo[tid] = __float2bfloat16_rn(w - __bfloat162float(hi));
}

// ---------------- graph-structure kernels ----------------
__global__ void k_count(const int* __restrict__ dst, int* __restrict__ degi, int e_cnt) {
    int e = blockIdx.x*256 + threadIdx.x;
    if (e < e_cnt) atomicAdd(&degi[dst[e]], 1);
}

__global__ void k_dinv(const int* __restrict__ degi, float* __restrict__ dinv, int n) {
    int i = blockIdx.x*256 + threadIdx.x;
    if (i < n) dinv[i] = rsqrtf((float)degi[i] + 1.0f);
}

__global__ void k_scan(const int* __restrict__ cnt, int* __restrict__ rowptr,
                       int* __restrict__ cursor, int n) {
    __shared__ int warpsum[32];
    __shared__ int carrySh;
    int t = threadIdx.x, lane = t & 31, w = t >> 5;
    if (t == 0) carrySh = 0;
    __syncthreads();
    for (int base = 0; base < n; base += 1024) {
        int i = base + t;
        int v = (i < n) ? cnt[i] : 0;
        int s = v;
        #pragma unroll
        for (int o = 1; o < 32; o <<= 1) { int u = __shfl_up_sync(~0u, s, o); if (lane >= o) s += u; }
        if (lane == 31) warpsum[w] = s;
        __syncthreads();
        if (w == 0) {
            int ws = warpsum[lane];
            #pragma unroll
            for (int o = 1; o < 32; o <<= 1) { int u = __shfl_up_sync(~0u, ws, o); if (lane >= o) ws += u; }
            warpsum[lane] = ws;
        }
        __syncthreads();
        int excl = carrySh + (w > 0 ? warpsum[w-1] : 0) + s - v;
        if (i < n) { rowptr[i] = excl; cursor[i] = excl; }
        __syncthreads();
        if (t == 0) carrySh += warpsum[31];
        __syncthreads();
    }
    if (threadIdx.x == 0) rowptr[n] = carrySh;
}

__global__ void k_scatter(const int* __restrict__ src, const int* __restrict__ dst,
                          int* __restrict__ cursor, int* __restrict__ srcs, int e_cnt) {
    int e = blockIdx.x*256 + threadIdx.x;
    if (e < e_cnt) {
        int d = dst[e];
        int pos = atomicAdd(&cursor[d], 1);
        srcs[pos] = src[e];
    }
}

__global__ void k_aggregate(const float* __restrict__ p, float* __restrict__ g,
                            const float* __restrict__ dinv,
                            const int* __restrict__ rowptr, const int* __restrict__ srcs,
                            const float* __restrict__ bgcn, int n) {
    int warp = (blockIdx.x*blockDim.x + threadIdx.x) >> 5;
    int lane = threadIdx.x & 31;
    if (warp >= n) return;
    int i = warp;
    float di = dinv[i];
    float4 ps = ((const float4*)(p + (size_t)i*DLAT))[lane];
    float sn = di*di;
    float4 acc;
    acc.x = ps.x*sn; acc.y = ps.y*sn; acc.z = ps.z*sn; acc.w = ps.w*sn;
    int beg = rowptr[i], end = rowptr[i+1];
    for (int e = beg; e < end; e++) {
        int s = srcs[e];
        float w = di * dinv[s];
        float4 v = ((const float4*)(p + (size_t)s*DLAT))[lane];
        acc.x += v.x*w; acc.y += v.y*w; acc.z += v.z*w; acc.w += v.w*w;
    }
    float4 b = ((const float4*)bgcn)[lane];
    acc.x += b.x; acc.y += b.y; acc.z += b.z; acc.w += b.w;
    ((float4*)(g + (size_t)i*DLAT))[lane] = acc;
}

// ---------------- shared device helpers ----------------
__device__ __forceinline__ void split4(float4 v, uint2& uh, uint2& ul) {
    __nv_bfloat162 h01 = __floats2bfloat162_rn(v.x, v.y);
    __nv_bfloat162 h23 = __floats2bfloat162_rn(v.z, v.w);
    float r0 = v.x - __bfloat162float(h01.x);
    float r1 = v.y - __bfloat162float(h01.y);
    float r2 = v.z - __bfloat162float(h23.x);
    float r3 = v.w - __bfloat162float(h23.y);
    __nv_bfloat162 l01 = __floats2bfloat162_rn(r0, r1);
    __nv_bfloat162 l23 = __floats2bfloat162_rn(r2, r3);
    uh.x = *reinterpret_cast<uint32_t*>(&h01); uh.y = *reinterpret_cast<uint32_t*>(&h23);
    ul.x = *reinterpret_cast<uint32_t*>(&l01); ul.y = *reinterpret_cast<uint32_t*>(&l23);
}

// ---------------- 512-thread bf16-split GEMM ----------------
// 16 warps (4x4), warp tile 32x32, whole-128-K window resident, XOR swizzle.
// ACT: 0 none, 1 sigmoid, 2 relu, 4 fused mu/std/reparam (interleaved N=256).
template<int ACT>
__global__ __launch_bounds__(512, 1)
void tc_gemm(const float* __restrict__ A,
             const __nv_bfloat16* __restrict__ Bhi_g,
             const __nv_bfloat16* __restrict__ Blo_g,
             const float* __restrict__ bias,
             const float* __restrict__ bias2,
             const float* __restrict__ epsp,
             float* __restrict__ C,
             float* __restrict__ C2,
             float* __restrict__ C3,
             int M, int K, int Nglobal) {
    extern __shared__ __nv_bfloat16 sm[];
    __nv_bfloat16* Ah = sm;
    __nv_bfloat16* Al = sm + 16384;
    __nv_bfloat16* Bh = sm + 32768;
    __nv_bfloat16* Bl = sm + 49152;
    uint32_t aHi = smem_u32(Ah), aLo = smem_u32(Al);
    uint32_t bHi = smem_u32(Bh), bLo = smem_u32(Bl);

    int t = threadIdx.x, lane = t & 31, warp = t >> 5;
    int wrow = (warp & 3) * 32, wcol = (warp >> 2) * 32;
    int rowBase = blockIdx.x * 128, colBase = blockIdx.y * 128;
    uint32_t l7 = (uint32_t)(lane & 7);

    float acc[2][4][4];
    #pragma unroll
    for (int i = 0; i < 2; i++)
        #pragma unroll
        for (int j = 0; j < 4; j++)
            #pragma unroll
            for (int q = 0; q < 4; q++) acc[i][j][q] = 0.f;

    for (int ko = 0; ko < K; ko += 128) {
        if (ko) __syncthreads();

        // B: cp.async (4096 x 16B, 8/thread)
        #pragma unroll
        for (int r = 0; r < 8; r++) {
            int pos = t + r*512;
            int g = pos & 7, row = (pos >> 3) & 127, chunk = (pos >> 10) & 1, hb = pos >> 11;
            int gk = ko + chunk*64 + g*8;
            int gn = colBase + row;
            bool ok = (gn < Nglobal) && (gk < K);
            const __nv_bfloat16* srcp = (hb ? Blo_g : Bhi_g) + (ok ? ((size_t)gn*K + gk) : 0);
            uint32_t dst = (hb ? bLo : bHi) + (uint32_t)(chunk*16384 + row*128
                          + (((uint32_t)g ^ (uint32_t)(row & 7)) << 4));
            CP_ASYNC16(dst, srcp, ok ? 16u : 0u);
        }

        // A: LDG fp32 -> split -> swizzled STS
        float4 av[8];
        #pragma unroll
        for (int r = 0; r < 8; r++) {
            int pos = t + r*512;
            int row = pos >> 5, c4 = pos & 31;
            int gr = rowBase + row, gc = ko + c4*4;
            av[r] = (gr < M && gc < K) ? *(const float4*)(A + (size_t)gr*K + gc)
                                       : make_float4(0.f, 0.f, 0.f, 0.f);
        }
        #pragma unroll
        for (int r = 0; r < 8; r++) {
            int pos = t + r*512;
            int row = pos >> 5, c4 = pos & 31;
            int chunk = c4 >> 4, lc4 = c4 & 15;
            uint2 uh, ul;
            split4(av[r], uh, ul);
            uint32_t off = (uint32_t)(chunk*16384 + row*128
                          + ((((uint32_t)(lc4 >> 1)) ^ (uint32_t)(row & 7)) << 4)
                          + ((lc4 & 1) << 3));
            *(uint2*)((char*)Ah + off) = uh;
            *(uint2*)((char*)Al + off) = ul;
        }

        CP_WAIT_ALL();
        __syncthreads();

        int ksteps = ((K - ko < 128) ? (K - ko) : 128) >> 4;
        for (int ks = 0; ks < ksteps; ks++) {
            int chunk = ks >> 2, kloc = ks & 3;
            uint32_t choff = (uint32_t)(chunk * 16384);
            uint32_t ah[2][4], al[2][4], bh[4][2], bl[4][2];
            uint32_t gA = ((uint32_t)(kloc*2) + (uint32_t)(lane >> 4)) ^ l7;
            uint32_t gB = ((uint32_t)(kloc*2) + (uint32_t)((lane >> 3) & 1)) ^ l7;
            #pragma unroll
            for (int mi = 0; mi < 2; mi++) {
                uint32_t row = (uint32_t)(wrow + mi*16 + (lane & 15));
                uint32_t off = choff + row*128 + (gA << 4);
                LDSM4(ah[mi][0], ah[mi][1], ah[mi][2], ah[mi][3], aHi + off);
                LDSM4(al[mi][0], al[mi][1], al[mi][2], al[mi][3], aLo + off);
            }
            #pragma unroll
            for (int np = 0; np < 2; np++) {
                uint32_t row = (uint32_t)(wcol + np*16 + ((lane >> 4) << 3) + (lane & 7));
                uint32_t off = choff + row*128 + (gB << 4);
                uint32_t r0, r1, r2, r3;
                LDSM4(r0, r1, r2, r3, bHi + off);
                bh[np*2][0] = r0; bh[np*2][1] = r1; bh[np*2+1][0] = r2; bh[np*2+1][1] = r3;
                LDSM4(r0, r1, r2, r3, bLo + off);
                bl[np*2][0] = r0; bl[np*2][1] = r1; bl[np*2+1][0] = r2; bl[np*2+1][1] = r3;
            }
            #pragma unroll
            for (int mi = 0; mi < 2; mi++)
                #pragma unroll
                for (int ni = 0; ni < 4; ni++) {
                    MMA16816(acc[mi][ni], ah[mi], bh[ni]);
                    MMA16816(acc[mi][ni], al[mi], bh[ni]);
                    MMA16816(acc[mi][ni], ah[mi], bl[ni]);
                }
        }
    }

    // ---- epilogue ----
    int r0base = rowBase + wrow + (lane >> 2);
    int c0base = colBase + wcol + (lane & 3)*2;
    #pragma unroll
    for (int mi = 0; mi < 2; mi++) {
        #pragma unroll
        for (int ni = 0; ni < 4; ni++) {
            int col = c0base + ni*8;
            float* cc = acc[mi][ni];
            if (ACT == 4) {
                int j = col >> 1;   // interleaved: even=mu, odd=std
                #pragma unroll
                for (int half = 0; half < 2; half++) {
                    int rr = r0base + mi*16 + half*8;
                    if (rr < M) {
                        float mu = cc[half*2] + bias[j];
                        float z  = cc[half*2+1] + bias2[j] - 5.f;
                        float sp = fmaxf(z, 0.f) + log1pf(__expf(-fabsf(z)));
                        size_t o = (size_t)rr*DLAT + j;
                        C[o]  = mu;
                        C2[o] = sp;
                        C3[o] = mu + sp*epsp[o];
                    }
                }
            } else {
                if (col < Nglobal) {
                    float b0 = bias ? bias[col]   : 0.f;
                    float b1 = bias ? bias[col+1] : 0.f;
                    #pragma unroll
                    for (int half = 0; half < 2; half++) {
                        int rr = r0base + mi*16 + half*8;
                        if (rr < M) {
                            float x0 = cc[half*2] + b0;
                            float x1 = cc[half*2+1] + b1;
                            if (ACT == 1) { x0 = 1.f/(1.f + __expf(-x0)); x1 = 1.f/(1.f + __expf(-x1)); }
                            else if (ACT == 2) { x0 = fmaxf(x0, 0.f); x1 = fmaxf(x1, 0.f); }
                            *(float2*)(C + (size_t)rr*Nglobal + col) = make_float2(x0, x1);
                        }
                    }
                }
            }
        }
    }
}

// ---------------- fused decoder tail ----------------
__global__ __launch_bounds__(256)
void k_dec_tail(const float* __restrict__ D, const float* __restrict__ W3,
                const float* __restrict__ b3, const float* __restrict__ W4,
                const float* __restrict__ b4, const float* __restrict__ Wo,
                const float* __restrict__ bo, const int* __restrict__ batch,
                float* __restrict__ gsum, int* __restrict__ gcnt, int n) {
    __shared__ float sW3[64*32], sW4[32*16], sWo[16*10];
    __shared__ float sb3[32], sb4[16], sbo[10];
    __shared__ float srow[8][64];
    int t = threadIdx.x;
    for (int i = t; i < 64*32; i += 256) sW3[i] = W3[i];
    for (int i = t; i < 32*16; i += 256) sW4[i] = W4[i];
    if (t < 160) sWo[t] = Wo[t];
    if (t < 32)  sb3[t] = b3[t];
    if (t < 16)  sb4[t] = b4[t];
    if (t < 10)  sbo[t] = bo[t];
    __syncthreads();
    int warp = t >> 5, lane = t & 31;
    int row = blockIdx.x*8 + warp;
    if (row >= n) return;
    srow[warp][lane]      = D[(size_t)row*64 + lane];
    srow[warp][lane + 32] = D[(size_t)row*64 + lane + 32];
    __syncwarp();
    float acc = sb3[lane];
    #pragma unroll 8
    for (int k = 0; k < 64; k++) acc += srow[warp][k]*sW3[k*32 + lane];
    float h3 = fmaxf(acc, 0.f);
    float acc4 = (lane < 16) ? sb4[lane] : 0.f;
    #pragma unroll
    for (int k = 0; k < 32; k++) {
        float a = __shfl_sync(0xffffffffu, h3, k);
        if (lane < 16) acc4 += a*sW4[k*16 + lane];
    }
    float h4 = fmaxf(acc4, 0.f);
    float acco = (lane < 10) ? sbo[lane] : 0.f;
    #pragma unroll
    for (int k = 0; k < 16; k++) {
        float a = __shfl_sync(0xffffffffu, h4, k);
        if (lane < 10) acco += a*sWo[k*10 + lane];
    }
    int b = batch[row];
    if (lane < 10) {
        float v = 1.f/(1.f + __expf(-acco));
        atomicAdd(&gsum[b*DOUTD + lane], v);
    }
    if (lane == 0) atomicAdd(&gcnt[b], 1);
}

__global__ void k_finalize(const float* __restrict__ gsum, const int* __restrict__ gcnt,
                           const float* __restrict__ y, float* __restrict__ out) {
    int i = blockIdx.x*256 + threadIdx.x;
    if (i < GG*DOUTD) {
        int gi = i / DOUTD;
        float c = (float)gcnt[gi];
        out[O_YPRED + i] = gsum[i] / fmaxf(c, 1.f);
        out[O_Y + i]     = y[i];
    }
}

// ---------------- host ----------------
static const __nv_bfloat16* g_whi;
static const __nv_bfloat16* g_wlo;
static constexpr int TC_SMEM = 131072;

static void launch_tc(int act, const float* A, int woff,
                      const float* b, const float* b2, const float* epsp,
                      float* C, float* C2, float* C3, int M, int K, int Ncol) {
    const __nv_bfloat16* bh = g_whi + woff;
    const __nv_bfloat16* bl = g_wlo + woff;
    dim3 grid((M + 127)/128, (Ncol + 127)/128);
    switch (act) {
    case 0:
        cudaFuncSetAttribute(tc_gemm<0>, cudaFuncAttributeMaxDynamicSharedMemorySize, TC_SMEM);
        tc_gemm<0><<<grid, 512, TC_SMEM>>>(A, bh, bl, b, b2, epsp, C, C2, C3, M, K, Ncol); break;
    case 1:
        cudaFuncSetAttribute(tc_gemm<1>, cudaFuncAttributeMaxDynamicSharedMemorySize, TC_SMEM);
        tc_gemm<1><<<grid, 512, TC_SMEM>>>(A, bh, bl, b, b2, epsp, C, C2, C3, M, K, Ncol); break;
    case 2:
        cudaFuncSetAttribute(tc_gemm<2>, cudaFuncAttributeMaxDynamicSharedMemorySize, TC_SMEM);
        tc_gemm<2><<<grid, 512, TC_SMEM>>>(A, bh, bl, b, b2, epsp, C, C2, C3, M, K, Ncol); break;
    case 4:
        cudaFuncSetAttribute(tc_gemm<4>, cudaFuncAttributeMaxDynamicSharedMemorySize, TC_SMEM);
        tc_gemm<4><<<grid, 512, TC_SMEM>>>(A, bh, bl, b, b2, epsp, C, C2, C3, M, K, Ncol); break;
    }
}

extern "C" void kernel_launch(void* const* d_in, const int* in_sizes, int n_in,
                              void* d_out, int out_size) {
    const float* x     = (const float*)d_in[0];
    const int*   eidx  = (const int*)  d_in[1];
    const int*   batch = (const int*)  d_in[2];
    const float* y     = (const float*)d_in[3];
    const float* eps   = (const float*)d_in[4];
    const float* W_in  = (const float*)d_in[5];
    const float* b_in  = (const float*)d_in[6];
    const float* W_gcn = (const float*)d_in[7];
    const float* b_gcn = (const float*)d_in[8];
    const float* W_enc = (const float*)d_in[9];
    const float* b_enc = (const float*)d_in[10];
    const float* W_mu  = (const float*)d_in[11];
    const float* b_mu  = (const float*)d_in[12];
    const float* W_std = (const float*)d_in[13];
    const float* b_std = (const float*)d_in[14];
    const float* Wd0 = (const float*)d_in[15]; const float* bd0 = (const float*)d_in[16];
    const float* Wd1 = (const float*)d_in[17]; const float* bd1 = (const float*)d_in[18];
    const float* Wd2 = (const float*)d_in[19]; const float* bd2 = (const float*)d_in[20];
    const float* Wd3 = (const float*)d_in[21]; const float* bd3 = (const float*)d_in[22];
    const float* Wd4 = (const float*)d_in[23]; const float* bd4 = (const float*)d_in[24];
    const float* Wo  = (const float*)d_in[25]; const float* bo  = (const float*)d_in[26];
    float* out = (float*)d_out;

    const int* e_src = eidx;
    const int* e_dst = eidx + EE;

    void* pv;
    cudaGetSymbolAddress(&pv, s_degi);   int*   degi   = (int*)pv;
    cudaGetSymbolAddress(&pv, s_dinv);   float* dinv   = (float*)pv;
    cudaGetSymbolAddress(&pv, s_rowptr); int*   rowptr = (int*)pv;
    cudaGetSymbolAddress(&pv, s_cursor); int*   cursor = (int*)pv;
    cudaGetSymbolAddress(&pv, s_srcs);   int*   srcs   = (int*)pv;
    cudaGetSymbolAddress(&pv, s_h);      float* h      = (float*)pv;
    cudaGetSymbolAddress(&pv, s_p);      float* p      = (float*)pv;
    cudaGetSymbolAddress(&pv, s_g);      float* g      = (float*)pv;
    cudaGetSymbolAddress(&pv, s_t);      float* tbuf   = (float*)pv;
    cudaGetSymbolAddress(&pv, s_dec);    float* dec    = (float*)pv;
    cudaGetSymbolAddress(&pv, s_gsum);   float* gsum   = (float*)pv;
    cudaGetSymbolAddress(&pv, s_gcnt);   int*   gcnt   = (int*)pv;
    cudaGetSymbolAddress(&pv, s_Whi);    __nv_bfloat16* whi = (__nv_bfloat16*)pv;
    cudaGetSymbolAddress(&pv, s_Wlo);    __nv_bfloat16* wlo = (__nv_bfloat16*)pv;
    g_whi = whi; g_wlo = wlo;

    float* outMu  = out + O_MU;
    float* outStd = out + O_STD;

    // [1] fused weight conversion
    k_wconv_all<<<(WPOOL_SZ + 255)/256, 256>>>(W_in, W_gcn, W_enc, W_mu, W_std,
                                               Wd0, Wd1, Wd2, whi, wlo);
    // [2-4] memsets
    cudaMemsetAsync(degi, 0, NN*sizeof(int), 0);
    cudaMemsetAsync(gsum, 0, GG*DOUTD*sizeof(float), 0);
    cudaMemsetAsync(gcnt, 0, GG*sizeof(int), 0);
    // [5] degree count
    k_count<<<(EE+255)/256, 256>>>(e_dst, degi, EE);
    // [6] input layer
    launch_tc(1, x, WOFF_IN, b_in, nullptr, nullptr, h, nullptr, nullptr, NN, DIN, DLAT);
    // [7] hop-0 GCN GEMM  <-- ncu capture target
    launch_tc(0, h, WOFF_GCN, nullptr, nullptr, nullptr, p, nullptr, nullptr, NN, DLAT, DLAT);
    // [8-10] CSR build
    k_dinv<<<(NN+255)/256, 256>>>(degi, dinv, NN);
    k_scan<<<1, 1024>>>(degi, rowptr, cursor, NN);
    k_scatter<<<(EE+255)/256, 256>>>(e_src, e_dst, cursor, srcs, EE);

    // ---- K hops (validated R4 structure, 512-thread GEMMs) ----
    for (int hop = 0; hop < KHOPS; hop++) {
        if (hop > 0)
            launch_tc(0, h, WOFF_GCN, nullptr, nullptr, nullptr, p, nullptr, nullptr, NN, DLAT, DLAT);
        k_aggregate<<<(NN*32 + 255)/256, 256>>>(p, g, dinv, rowptr, srcs, b_gcn, NN);
        float* cur = g; float* other = tbuf;
        for (int j = 0; j < 5; j++) {
            launch_tc(1, cur, WOFF_ENC + j*DLAT*DLAT, b_enc + j*DLAT, nullptr, nullptr,
                      other, nullptr, nullptr, NN, DLAT, DLAT);
            float* tmp = cur; cur = other; other = tmp;
        }
        launch_tc(4, cur, WOFF_MUSTD, b_mu, b_std, eps + (size_t)hop*NN*DLAT,
                  outMu, outStd, h, NN, DLAT, 256);
    }

    // ---- decoder ----
    launch_tc(2, h,   WOFF_D0, bd0, nullptr, nullptr, dec,  nullptr, nullptr, NN, DLAT, 256);
    launch_tc(2, dec, WOFF_D1, bd1, nullptr, nullptr, g,    nullptr, nullptr, NN, 256,  DLAT);
    launch_tc(2, g,   WOFF_D2, bd2, nullptr, nullptr, tbuf, nullptr, nullptr, NN, DLAT, 64);
    k_dec_tail<<<(NN+7)/8, 256>>>(tbuf, Wd3, bd3, Wd4, bd4, Wo, bo, batch, gsum, gcnt, NN);
    k_finalize<<<(GG*DOUTD + 255)/256, 256>>>(gsum, gcnt, y, out);
}